// round 11
// baseline (speedup 1.0000x reference)
#include <cuda_runtime.h>
#include <math.h>
#include <stdint.h>

#define NSEQ 320
#define C 128
#define H 4
#define D 32
#define NN (NSEQ*NSEQ)        // 102400
#define LN_EPS 1e-5f

// ---- scratch (device globals; no allocation). hi/lo = tf32 split pairs ----
__device__ float g_xhi[NN*C], g_xlo[NN*C];
__device__ float g_q[NN*C];                    // fp32 (split at attn preload)
__device__ float g_khi[NN*C], g_klo[NN*C];
__device__ float g_vhi[NN*C], g_vlo[NN*C];
__device__ float g_gate[NN*C];
__device__ float g_wahi[NN*C], g_walo[NN*C];
__device__ float g_bias[H*NN];                 // [h][k][q]
__device__ int   g_idx[NN];
__device__ int   g_cnt[NSEQ];
__device__ float g_wsphi[4*C*C], g_wsplo[4*C*C];   // wq,wk,wv,wg
__device__ float g_wohi[C*C],   g_wolo[C*C];       // wout

// ---------- tf32 helpers ----------
__device__ __forceinline__ uint32_t tf32b(float x) {
    uint32_t u; asm("cvt.rna.tf32.f32 %0, %1;" : "=r"(u) : "f"(x)); return u;
}
__device__ __forceinline__ void split_tf32(float x, uint32_t& hi, uint32_t& lo) {
    hi = tf32b(x);
    lo = tf32b(x - __uint_as_float(hi));
}
__device__ __forceinline__ void mma8(float* d_, const uint32_t* a, const uint32_t* b) {
    asm volatile(
        "mma.sync.aligned.m16n8k8.row.col.f32.tf32.tf32.f32 "
        "{%0,%1,%2,%3}, {%4,%5,%6,%7}, {%8,%9}, {%0,%1,%2,%3};"
        : "+f"(d_[0]), "+f"(d_[1]), "+f"(d_[2]), "+f"(d_[3])
        : "r"(a[0]), "r"(a[1]), "r"(a[2]), "r"(a[3]), "r"(b[0]), "r"(b[1]));
}

// ============================================================
// Kernel 0a: compaction of valid k columns per b.
// ============================================================
__global__ void compact_kernel(const int* __restrict__ pm) {
    int b = blockIdx.x;
    int t = threadIdx.x;
    __shared__ int wcnt[10], woff[10];
    int valid = (pm[(size_t)t * NSEQ + b] > 0) ? 1 : 0;
    unsigned ball = __ballot_sync(0xffffffffu, valid);
    int warp = t >> 5, lane = t & 31;
    if (lane == 0) wcnt[warp] = __popc(ball);
    __syncthreads();
    if (t == 0) {
        int s = 0;
        #pragma unroll
        for (int w = 0; w < 10; w++) { woff[w] = s; s += wcnt[w]; }
        g_cnt[b] = s;
    }
    __syncthreads();
    if (valid) {
        int pos = woff[warp] + __popc(ball & ((1u << lane) - 1u));
        g_idx[b * NSEQ + pos] = t;
    }
}

// ============================================================
// Kernel 0b: pre-split weights to tf32 hi/lo.
// ============================================================
__global__ void wsplit(const float* __restrict__ wq, const float* __restrict__ wk,
                       const float* __restrict__ wv, const float* __restrict__ wg,
                       const float* __restrict__ wout) {
    int i = blockIdx.x * 256 + threadIdx.x;
    if (i >= C*C) return;
    const float* srcs[4] = { wq, wk, wv, wg };
    #pragma unroll
    for (int s = 0; s < 4; s++) {
        uint32_t hi, lo; split_tf32(srcs[s][i], hi, lo);
        g_wsphi[s*C*C + i] = __uint_as_float(hi);
        g_wsplo[s*C*C + i] = __uint_as_float(lo);
    }
    uint32_t hi, lo; split_tf32(wout[i], hi, lo);
    g_wohi[i] = __uint_as_float(hi);
    g_wolo[i] = __uint_as_float(lo);
}

// ============================================================
// Kernel 1: LayerNorm (writes tf32 hi/lo) + pair-bias.
// ============================================================
__global__ void ln_bias_kernel(const float* __restrict__ act,
                               const float* __restrict__ gamma,
                               const float* __restrict__ beta,
                               const float* __restrict__ wpb) {
    int warp = (blockIdx.x * blockDim.x + threadIdx.x) >> 5;
    int lane = threadIdx.x & 31;
    if (warp >= NN) return;
    const float4* a = (const float4*)(act + (size_t)warp * C);
    float4 v = a[lane];
    float s  = v.x + v.y + v.z + v.w;
    float s2 = v.x*v.x + v.y*v.y + v.z*v.z + v.w*v.w;
    #pragma unroll
    for (int o = 16; o > 0; o >>= 1) {
        s  += __shfl_xor_sync(0xffffffffu, s,  o);
        s2 += __shfl_xor_sync(0xffffffffu, s2, o);
    }
    float mu  = s * (1.0f / C);
    float var = s2 * (1.0f / C) - mu * mu;
    float r = rsqrtf(var + LN_EPS);
    float4 g = ((const float4*)gamma)[lane];
    float4 b = ((const float4*)beta)[lane];
    float4 o;
    o.x = (v.x - mu) * r * g.x + b.x;
    o.y = (v.y - mu) * r * g.y + b.y;
    o.z = (v.z - mu) * r * g.z + b.z;
    o.w = (v.w - mu) * r * g.w + b.w;
    float4 oh, ol;
    uint32_t th, tl;
    split_tf32(o.x, th, tl); oh.x = __uint_as_float(th); ol.x = __uint_as_float(tl);
    split_tf32(o.y, th, tl); oh.y = __uint_as_float(th); ol.y = __uint_as_float(tl);
    split_tf32(o.z, th, tl); oh.z = __uint_as_float(th); ol.z = __uint_as_float(tl);
    split_tf32(o.w, th, tl); oh.w = __uint_as_float(th); ol.w = __uint_as_float(tl);
    ((float4*)(g_xhi + (size_t)warp * C))[lane] = oh;
    ((float4*)(g_xlo + (size_t)warp * C))[lane] = ol;

    const float4* wb = (const float4*)(wpb + lane * 16);
    float4 w0 = wb[0], w1 = wb[1], w2 = wb[2], w3 = wb[3];
    float bh[4];
    bh[0] = o.x*w0.x + o.y*w1.x + o.z*w2.x + o.w*w3.x;
    bh[1] = o.x*w0.y + o.y*w1.y + o.z*w2.y + o.w*w3.y;
    bh[2] = o.x*w0.z + o.y*w1.z + o.z*w2.z + o.w*w3.z;
    bh[3] = o.x*w0.w + o.y*w1.w + o.z*w2.w + o.w*w3.w;
    #pragma unroll
    for (int h = 0; h < 4; h++) {
        #pragma unroll
        for (int off = 16; off > 0; off >>= 1)
            bh[h] += __shfl_xor_sync(0xffffffffu, bh[h], off);
    }
    if (lane == 0) {
        int qi = warp / NSEQ;
        int kj = warp - qi * NSEQ;
        #pragma unroll
        for (int h = 0; h < 4; h++)
            g_bias[h*NN + kj*NSEQ + qi] = bh[h];
    }
}

// ============================================================
// Kernel 2: projection GEMMs, pre-split operands, BK=16.
// grid (4 ops, 800 m-tiles), 256 thr = 8 warps (2m x 4n).
// ============================================================
__global__ void __launch_bounds__(256)
proj_mma() {
    __shared__ __align__(16) float2 As2[128][20];
    __shared__ __align__(16) float2 Bs2[16][132];
    int op = blockIdx.x;
    const float* Whi = g_wsphi + op * C * C;
    const float* Wlo = g_wsplo + op * C * C;
    int bm = blockIdx.y * 128;
    int tid = threadIdx.x;
    int wid = tid >> 5, lane = tid & 31;
    int wm = (wid >> 2) * 64, wn = (wid & 3) * 32;
    int lr = lane >> 2, lc = lane & 3;

    float acc[4][4][4];
    #pragma unroll
    for (int mi = 0; mi < 4; mi++)
        #pragma unroll
        for (int ni = 0; ni < 4; ni++)
            #pragma unroll
            for (int e = 0; e < 4; e++) acc[mi][ni][e] = 0.0f;

    for (int k0 = 0; k0 < C; k0 += 16) {
        #pragma unroll
        for (int i = 0; i < 2; i++) {       // A: 128x16
            int e = i * 256 + tid;
            int r = e >> 2, c4 = (e & 3) * 4;
            float4 xh = *(const float4*)(g_xhi + (size_t)(bm + r) * C + k0 + c4);
            float4 xl = *(const float4*)(g_xlo + (size_t)(bm + r) * C + k0 + c4);
            As2[r][c4+0] = make_float2(xh.x, xl.x);
            As2[r][c4+1] = make_float2(xh.y, xl.y);
            As2[r][c4+2] = make_float2(xh.z, xl.z);
            As2[r][c4+3] = make_float2(xh.w, xl.w);
        }
        #pragma unroll
        for (int i = 0; i < 2; i++) {       // B: 16x128
            int e = i * 256 + tid;
            int r = e >> 5, c4 = (e & 31) * 4;
            float4 wh = *(const float4*)(Whi + (size_t)(k0 + r) * C + c4);
            float4 wl = *(const float4*)(Wlo + (size_t)(k0 + r) * C + c4);
            Bs2[r][c4+0] = make_float2(wh.x, wl.x);
            Bs2[r][c4+1] = make_float2(wh.y, wl.y);
            Bs2[r][c4+2] = make_float2(wh.z, wl.z);
            Bs2[r][c4+3] = make_float2(wh.w, wl.w);
        }
        __syncthreads();
        #pragma unroll
        for (int kc = 0; kc < 2; kc++) {
            int kb = kc * 8 + lc;
            uint32_t ahi[4][4], alo[4][4];
            #pragma unroll
            for (int mi = 0; mi < 4; mi++) {
                int r0 = wm + mi * 16 + lr;
                float2 f0 = As2[r0][kb],     f1 = As2[r0+8][kb];
                float2 f2 = As2[r0][kb+4],   f3 = As2[r0+8][kb+4];
                ahi[mi][0] = __float_as_uint(f0.x); alo[mi][0] = __float_as_uint(f0.y);
                ahi[mi][1] = __float_as_uint(f1.x); alo[mi][1] = __float_as_uint(f1.y);
                ahi[mi][2] = __float_as_uint(f2.x); alo[mi][2] = __float_as_uint(f2.y);
                ahi[mi][3] = __float_as_uint(f3.x); alo[mi][3] = __float_as_uint(f3.y);
            }
            uint32_t bhi[4][2], blo[4][2];
            #pragma unroll
            for (int ni = 0; ni < 4; ni++) {
                int n0 = wn + ni * 8 + lr;
                float2 f0 = Bs2[kb][n0], f1 = Bs2[kb+4][n0];
                bhi[ni][0] = __float_as_uint(f0.x); blo[ni][0] = __float_as_uint(f0.y);
                bhi[ni][1] = __float_as_uint(f1.x); blo[ni][1] = __float_as_uint(f1.y);
            }
            #pragma unroll
            for (int mi = 0; mi < 4; mi++)
                #pragma unroll
                for (int ni = 0; ni < 4; ni++) {
                    mma8(acc[mi][ni], ahi[mi], bhi[ni]);
                    mma8(acc[mi][ni], ahi[mi], blo[ni]);
                    mma8(acc[mi][ni], alo[mi], bhi[ni]);
                }
        }
        __syncthreads();
    }

    const float qscale = 0.17677669529663687f;
    #pragma unroll
    for (int mi = 0; mi < 4; mi++) {
        #pragma unroll
        for (int ni = 0; ni < 4; ni++) {
            int row = bm + wm + mi * 16 + lr;
            int col = wn + ni * 8 + 2 * lc;
            float v0 = acc[mi][ni][0], v1 = acc[mi][ni][1];
            float v2 = acc[mi][ni][2], v3 = acc[mi][ni][3];
            size_t o0 = (size_t)row * C + col;
            size_t o1 = (size_t)(row + 8) * C + col;
            if (op == 0) {
                *(float2*)(g_q + o0) = make_float2(v0*qscale, v1*qscale);
                *(float2*)(g_q + o1) = make_float2(v2*qscale, v3*qscale);
            } else if (op == 3) {
                *(float2*)(g_gate + o0) = make_float2(1.0f/(1.0f+__expf(-v0)),
                                                      1.0f/(1.0f+__expf(-v1)));
                *(float2*)(g_gate + o1) = make_float2(1.0f/(1.0f+__expf(-v2)),
                                                      1.0f/(1.0f+__expf(-v3)));
            } else {
                float* dhi = (op == 1) ? g_khi : g_vhi;
                float* dlo = (op == 1) ? g_klo : g_vlo;
                uint32_t h0,l0,h1,l1,h2,l2,h3,l3;
                split_tf32(v0,h0,l0); split_tf32(v1,h1,l1);
                split_tf32(v2,h2,l2); split_tf32(v3,h3,l3);
                *(float2*)(dhi + o0) = make_float2(__uint_as_float(h0), __uint_as_float(h1));
                *(float2*)(dlo + o0) = make_float2(__uint_as_float(l0), __uint_as_float(l1));
                *(float2*)(dhi + o1) = make_float2(__uint_as_float(h2), __uint_as_float(h3));
                *(float2*)(dlo + o1) = make_float2(__uint_as_float(l2), __uint_as_float(l3));
            }
        }
    }
}

// ============================================================
// Kernel 3: tensor attention. One block per (b,h), 320 thr = 10 warps.
// Pre-split K/V; bias loaded straight into accumulator from L2.
// ============================================================
#define KC 16

__global__ void __launch_bounds__(320, 1)
attn_mma() {
    __shared__ __align__(16) float2 Ks2[KC][34];   // [key][d] (hi,lo)
    __shared__ __align__(16) float2 Vt2[D][17];    // [d][key] (hi,lo)
    __shared__ float Ps[10][32][17];               // per-warp P
    __shared__ int idxs[KC];

    int b = blockIdx.x, h = blockIdx.y;
    int tid = threadIdx.x, wid = tid >> 5, lane = tid & 31;
    int lr = lane >> 2, lc = lane & 3;
    int cnt = g_cnt[b];
    const int* idxp = g_idx + b * NSEQ;
    const float* bhp = g_bias + (size_t)h * NN;
    int qbl = wid * 32;

    // Q fragments (split once)
    uint32_t qhi[2][4][4], qlo[2][4][4];
    {
        const float* qp = g_q + (size_t)(b * NSEQ) * C + h * D;
        #pragma unroll
        for (int mi = 0; mi < 2; mi++) {
            int r0 = qbl + mi * 16 + lr;
            #pragma unroll
            for (int kcc = 0; kcc < 4; kcc++) {
                int c0 = kcc * 8 + lc;
                split_tf32(qp[(size_t)r0 * C + c0],         qhi[mi][kcc][0], qlo[mi][kcc][0]);
                split_tf32(qp[(size_t)(r0 + 8) * C + c0],   qhi[mi][kcc][1], qlo[mi][kcc][1]);
                split_tf32(qp[(size_t)r0 * C + c0 + 4],     qhi[mi][kcc][2], qlo[mi][kcc][2]);
                split_tf32(qp[(size_t)(r0 + 8) * C + c0+4], qhi[mi][kcc][3], qlo[mi][kcc][3]);
            }
        }
    }

    float acc[2][4][4];
    #pragma unroll
    for (int mi = 0; mi < 2; mi++)
        #pragma unroll
        for (int ni = 0; ni < 4; ni++)
            #pragma unroll
            for (int e = 0; e < 4; e++) acc[mi][ni][e] = 0.0f;
    float lsum[2][2] = {{0.0f, 0.0f}, {0.0f, 0.0f}};

    int nch = (cnt + KC - 1) >> 4;
    for (int ch = 0; ch < nch; ch++) {
        int jc = ch << 4;
        __syncthreads();
        if (tid < KC) idxs[tid] = (jc + tid < cnt) ? idxp[jc + tid] : idxp[0];
        if (tid < 128) {
            int key = tid >> 3, dd = (tid & 7) * 4;
            int j = jc + key;
            int kg = (j < cnt) ? idxp[j] : idxp[0];
            size_t base = ((size_t)(b * NSEQ) + kg) * C + h * D + dd;
            float4 kh = *(const float4*)(g_khi + base);
            float4 kl = *(const float4*)(g_klo + base);
            Ks2[key][dd+0] = make_float2(kh.x, kl.x);
            Ks2[key][dd+1] = make_float2(kh.y, kl.y);
            Ks2[key][dd+2] = make_float2(kh.z, kl.z);
            Ks2[key][dd+3] = make_float2(kh.w, kl.w);
            float4 vh = *(const float4*)(g_vhi + base);
            float4 vl = *(const float4*)(g_vlo + base);
            Vt2[dd+0][key] = make_float2(vh.x, vl.x);
            Vt2[dd+1][key] = make_float2(vh.y, vl.y);
            Vt2[dd+2][key] = make_float2(vh.z, vl.z);
            Vt2[dd+3][key] = make_float2(vh.w, vl.w);
        }
        __syncthreads();

        // bias -> accumulator (pad keys get -1e4 => exp underflows to exact 0)
        float sc[2][2][4];
        #pragma unroll
        for (int ni = 0; ni < 2; ni++) {
            int kl_ = ni * 8 + 2 * lc;
            bool ok0 = (jc + kl_ < cnt), ok1 = (jc + kl_ + 1 < cnt);
            int kg0 = idxs[kl_], kg1 = idxs[kl_ + 1];
            #pragma unroll
            for (int mi = 0; mi < 2; mi++) {
                int q0 = qbl + mi * 16 + lr;
                sc[mi][ni][0] = ok0 ? bhp[(size_t)kg0 * NSEQ + q0]     : -1e4f;
                sc[mi][ni][1] = ok1 ? bhp[(size_t)kg1 * NSEQ + q0]     : -1e4f;
                sc[mi][ni][2] = ok0 ? bhp[(size_t)kg0 * NSEQ + q0 + 8] : -1e4f;
                sc[mi][ni][3] = ok1 ? bhp[(size_t)kg1 * NSEQ + q0 + 8] : -1e4f;
            }
        }
        // S = Q K^T + bias
        #pragma unroll
        for (int kcc = 0; kcc < 4; kcc++) {
            uint32_t bh2[2][2], bl2[2][2];
            #pragma unroll
            for (int ni = 0; ni < 2; ni++) {
                int n0 = ni * 8 + lr, kb = kcc * 8 + lc;
                float2 f0 = Ks2[n0][kb], f1 = Ks2[n0][kb + 4];
                bh2[ni][0] = __float_as_uint(f0.x); bl2[ni][0] = __float_as_uint(f0.y);
                bh2[ni][1] = __float_as_uint(f1.x); bl2[ni][1] = __float_as_uint(f1.y);
            }
            #pragma unroll
            for (int mi = 0; mi < 2; mi++)
                #pragma unroll
                for (int ni = 0; ni < 2; ni++) {
                    mma8(sc[mi][ni], qhi[mi][kcc], bh2[ni]);
                    mma8(sc[mi][ni], qhi[mi][kcc], bl2[ni]);
                    mma8(sc[mi][ni], qlo[mi][kcc], bh2[ni]);
                }
        }
        // exp + stash P
        #pragma unroll
        for (int mi = 0; mi < 2; mi++)
            #pragma unroll
            for (int ni = 0; ni < 2; ni++) {
                float p0 = __expf(sc[mi][ni][0]);
                float p1 = __expf(sc[mi][ni][1]);
                float p2 = __expf(sc[mi][ni][2]);
                float p3 = __expf(sc[mi][ni][3]);
                lsum[mi][0] += p0 + p1;
                lsum[mi][1] += p2 + p3;
                int r0 = mi * 16 + lr, cc = ni * 8 + 2 * lc;
                Ps[wid][r0][cc] = p0;     Ps[wid][r0][cc + 1] = p1;
                Ps[wid][r0 + 8][cc] = p2; Ps[wid][r0 + 8][cc + 1] = p3;
            }
        __syncwarp();
        // O += P V
        #pragma unroll
        for (int kcc = 0; kcc < 2; kcc++) {
            uint32_t phi[2][4], plo[2][4];
            #pragma unroll
            for (int mi = 0; mi < 2; mi++) {
                int r0 = mi * 16 + lr, kb = kcc * 8 + lc;
                split_tf32(Ps[wid][r0][kb],         phi[mi][0], plo[mi][0]);
                split_tf32(Ps[wid][r0 + 8][kb],     phi[mi][1], plo[mi][1]);
                split_tf32(Ps[wid][r0][kb + 4],     phi[mi][2], plo[mi][2]);
                split_tf32(Ps[wid][r0 + 8][kb + 4], phi[mi][3], plo[mi][3]);
            }
            #pragma unroll
            for (int ni = 0; ni < 4; ni++) {
                int n0 = ni * 8 + lr, kb = kcc * 8 + lc;
                float2 v0 = Vt2[n0][kb], v1 = Vt2[n0][kb + 4];
                uint32_t vh2[2] = { __float_as_uint(v0.x), __float_as_uint(v1.x) };
                uint32_t vl2[2] = { __float_as_uint(v0.y), __float_as_uint(v1.y) };
                #pragma unroll
                for (int mi = 0; mi < 2; mi++) {
                    mma8(acc[mi][ni], phi[mi], vh2);
                    mma8(acc[mi][ni], phi[mi], vl2);
                    mma8(acc[mi][ni], plo[mi], vh2);
                }
            }
        }
        __syncwarp();
    }

    // normalize + gate + write pre-split wa
    float inv[2][2];
    #pragma unroll
    for (int mi = 0; mi < 2; mi++)
        #pragma unroll
        for (int e = 0; e < 2; e++) {
            float lf = lsum[mi][e];
            lf += __shfl_xor_sync(0xffffffffu, lf, 1);
            lf += __shfl_xor_sync(0xffffffffu, lf, 2);
            inv[mi][e] = (lf > 0.0f) ? 1.0f / lf : 0.0f;
        }
    #pragma unroll
    for (int mi = 0; mi < 2; mi++) {
        int qg = b * NSEQ + qbl + mi * 16 + lr;
        #pragma unroll
        for (int ni = 0; ni < 4; ni++) {
            int dcol = h * D + ni * 8 + 2 * lc;
            size_t o0 = (size_t)qg * C + dcol;
            size_t o1 = o0 + (size_t)8 * C;
            float2 gt0 = *(const float2*)(g_gate + o0);
            float2 gt1 = *(const float2*)(g_gate + o1);
            float v0 = acc[mi][ni][0] * inv[mi][0] * gt0.x;
            float v1 = acc[mi][ni][1] * inv[mi][0] * gt0.y;
            float v2 = acc[mi][ni][2] * inv[mi][1] * gt1.x;
            float v3 = acc[mi][ni][3] * inv[mi][1] * gt1.y;
            uint32_t h0,l0,h1,l1,h2,l2,h3,l3;
            split_tf32(v0,h0,l0); split_tf32(v1,h1,l1);
            split_tf32(v2,h2,l2); split_tf32(v3,h3,l3);
            *(float2*)(g_wahi + o0) = make_float2(__uint_as_float(h0), __uint_as_float(h1));
            *(float2*)(g_walo + o0) = make_float2(__uint_as_float(l0), __uint_as_float(l1));
            *(float2*)(g_wahi + o1) = make_float2(__uint_as_float(h2), __uint_as_float(h3));
            *(float2*)(g_walo + o1) = make_float2(__uint_as_float(l2), __uint_as_float(l3));
        }
    }
}

// ============================================================
// Kernel 4: output GEMM, pre-split operands, BK=16.
// ============================================================
__global__ void __launch_bounds__(256)
out_mma(float* __restrict__ out) {
    __shared__ __align__(16) float2 As2[128][20];
    __shared__ __align__(16) float2 Bs2[128][20];   // [n][k]
    int bm = blockIdx.x * 128;
    int tid = threadIdx.x;
    int wid = tid >> 5, lane = tid & 31;
    int wm = (wid >> 2) * 64, wn = (wid & 3) * 32;
    int lr = lane >> 2, lc = lane & 3;

    float acc[4][4][4];
    #pragma unroll
    for (int mi = 0; mi < 4; mi++)
        #pragma unroll
        for (int ni = 0; ni < 4; ni++)
            #pragma unroll
            for (int e = 0; e < 4; e++) acc[mi][ni][e] = 0.0f;

    for (int k0 = 0; k0 < C; k0 += 16) {
        #pragma unroll
        for (int i = 0; i < 2; i++) {
            int e = i * 256 + tid;
            int r = e >> 2, c4 = (e & 3) * 4;
            float4 ah = *(const float4*)(g_wahi + (size_t)(bm + r) * C + k0 + c4);
            float4 al = *(const float4*)(g_walo + (size_t)(bm + r) * C + k0 + c4);
            As2[r][c4+0] = make_float2(ah.x, al.x);
            As2[r][c4+1] = make_float2(ah.y, al.y);
            As2[r][c4+2] = make_float2(ah.z, al.z);
            As2[r][c4+3] = make_float2(ah.w, al.w);
            float4 bh = *(const float4*)(g_wohi + (size_t)r * C + k0 + c4);
            float4 bl = *(const float4*)(g_wolo + (size_t)r * C + k0 + c4);
            Bs2[r][c4+0] = make_float2(bh.x, bl.x);
            Bs2[r][c4+1] = make_float2(bh.y, bl.y);
            Bs2[r][c4+2] = make_float2(bh.z, bl.z);
            Bs2[r][c4+3] = make_float2(bh.w, bl.w);
        }
        __syncthreads();
        #pragma unroll
        for (int kc = 0; kc < 2; kc++) {
            int kb = kc * 8 + lc;
            uint32_t ahi[4][4], alo[4][4];
            #pragma unroll
            for (int mi = 0; mi < 4; mi++) {
                int r0 = wm + mi * 16 + lr;
                float2 f0 = As2[r0][kb],   f1 = As2[r0+8][kb];
                float2 f2 = As2[r0][kb+4], f3 = As2[r0+8][kb+4];
                ahi[mi][0] = __float_as_uint(f0.x); alo[mi][0] = __float_as_uint(f0.y);
                ahi[mi][1] = __float_as_uint(f1.x); alo[mi][1] = __float_as_uint(f1.y);
                ahi[mi][2] = __float_as_uint(f2.x); alo[mi][2] = __float_as_uint(f2.y);
                ahi[mi][3] = __float_as_uint(f3.x); alo[mi][3] = __float_as_uint(f3.y);
            }
            uint32_t bhi[4][2], blo[4][2];
            #pragma unroll
            for (int ni = 0; ni < 4; ni++) {
                int n0 = wn + ni * 8 + lr;
                float2 f0 = Bs2[n0][kb], f1 = Bs2[n0][kb+4];
                bhi[ni][0] = __float_as_uint(f0.x); blo[ni][0] = __float_as_uint(f0.y);
                bhi[ni][1] = __float_as_uint(f1.x); blo[ni][1] = __float_as_uint(f1.y);
            }
            #pragma unroll
            for (int mi = 0; mi < 4; mi++)
                #pragma unroll
                for (int ni = 0; ni < 4; ni++) {
                    mma8(acc[mi][ni], ahi[mi], bhi[ni]);
                    mma8(acc[mi][ni], ahi[mi], blo[ni]);
                    mma8(acc[mi][ni], alo[mi], bhi[ni]);
                }
        }
        __syncthreads();
    }

    #pragma unroll
    for (int mi = 0; mi < 4; mi++) {
        #pragma unroll
        for (int ni = 0; ni < 4; ni++) {
            int row = bm + wm + mi * 16 + lr;
            int col = wn + ni * 8 + 2 * lc;
            *(float2*)(out + (size_t)row * C + col)
                = make_float2(acc[mi][ni][0], acc[mi][ni][1]);
            *(float2*)(out + (size_t)(row+8) * C + col)
                = make_float2(acc[mi][ni][2], acc[mi][ni][3]);
        }
    }
}

// ============================================================
extern "C" void kernel_launch(void* const* d_in, const int* in_sizes, int n_in,
                              void* d_out, int out_size) {
    const float* act   = (const float*)d_in[0];
    const int*   pmask = (const int*)  d_in[1];
    const float* gamma = (const float*)d_in[2];
    const float* beta  = (const float*)d_in[3];
    const float* wpb   = (const float*)d_in[4];
    const float* wq    = (const float*)d_in[5];
    const float* wk    = (const float*)d_in[6];
    const float* wv    = (const float*)d_in[7];
    const float* wg    = (const float*)d_in[8];
    const float* wout  = (const float*)d_in[9];
    float* out = (float*)d_out;

    compact_kernel<<<NSEQ, NSEQ>>>(pmask);
    wsplit<<<(C*C + 255)/256, 256>>>(wq, wk, wv, wg, wout);
    ln_bias_kernel<<<NN/8, 256>>>(act, gamma, beta, wpb);
    proj_mma<<<dim3(4, NN/128), 256>>>();
    attn_mma<<<dim3(NSEQ, H), 320>>>();
    out_mma<<<NN/128, 256>>>(out);
}

// round 12
// speedup vs baseline: 1.2029x; 1.2029x over previous
#include <cuda_runtime.h>
#include <math.h>
#include <stdint.h>

#define NSEQ 320
#define C 128
#define H 4
#define D 32
#define NN (NSEQ*NSEQ)        // 102400
#define LN_EPS 1e-5f

// ---- scratch (device globals). hi/lo = tf32 split planes ----
__device__ float g_xhi[NN*C], g_xlo[NN*C];
__device__ float g_q[NN*C];
__device__ float g_khi[NN*C], g_klo[NN*C];
__device__ float g_vhi[NN*C], g_vlo[NN*C];
__device__ float g_gate[NN*C];
__device__ float g_wahi[NN*C], g_walo[NN*C];
__device__ float g_bias[H*NN];                 // [h][k][q]
__device__ int   g_idx[NN];
__device__ int   g_cnt[NSEQ];
__device__ float g_wsphi[4*C*C], g_wsplo[4*C*C];
__device__ float g_wohi[C*C],   g_wolo[C*C];

// ---------- tf32 helpers ----------
__device__ __forceinline__ uint32_t tf32b(float x) {
    uint32_t u; asm("cvt.rna.tf32.f32 %0, %1;" : "=r"(u) : "f"(x)); return u;
}
__device__ __forceinline__ void split_tf32(float x, uint32_t& hi, uint32_t& lo) {
    hi = tf32b(x);
    lo = tf32b(x - __uint_as_float(hi));
}
__device__ __forceinline__ void mma8(float* d_, const uint32_t* a, const uint32_t* b) {
    asm volatile(
        "mma.sync.aligned.m16n8k8.row.col.f32.tf32.tf32.f32 "
        "{%0,%1,%2,%3}, {%4,%5,%6,%7}, {%8,%9}, {%0,%1,%2,%3};"
        : "+f"(d_[0]), "+f"(d_[1]), "+f"(d_[2]), "+f"(d_[3])
        : "r"(a[0]), "r"(a[1]), "r"(a[2]), "r"(a[3]), "r"(b[0]), "r"(b[1]));
}

// ============================================================
// Kernel 0a: compaction of valid k columns per b.
// ============================================================
__global__ void compact_kernel(const int* __restrict__ pm) {
    int b = blockIdx.x;
    int t = threadIdx.x;
    __shared__ int wcnt[10], woff[10];
    int valid = (pm[(size_t)t * NSEQ + b] > 0) ? 1 : 0;
    unsigned ball = __ballot_sync(0xffffffffu, valid);
    int warp = t >> 5, lane = t & 31;
    if (lane == 0) wcnt[warp] = __popc(ball);
    __syncthreads();
    if (t == 0) {
        int s = 0;
        #pragma unroll
        for (int w = 0; w < 10; w++) { woff[w] = s; s += wcnt[w]; }
        g_cnt[b] = s;
    }
    __syncthreads();
    if (valid) {
        int pos = woff[warp] + __popc(ball & ((1u << lane) - 1u));
        g_idx[b * NSEQ + pos] = t;
    }
}

// ============================================================
// Kernel 0b: pre-split weights.
// ============================================================
__global__ void wsplit(const float* __restrict__ wq, const float* __restrict__ wk,
                       const float* __restrict__ wv, const float* __restrict__ wg,
                       const float* __restrict__ wout) {
    int i = blockIdx.x * 256 + threadIdx.x;
    if (i >= C*C) return;
    const float* srcs[4] = { wq, wk, wv, wg };
    #pragma unroll
    for (int s = 0; s < 4; s++) {
        uint32_t hi, lo; split_tf32(srcs[s][i], hi, lo);
        g_wsphi[s*C*C + i] = __uint_as_float(hi);
        g_wsplo[s*C*C + i] = __uint_as_float(lo);
    }
    uint32_t hi, lo; split_tf32(wout[i], hi, lo);
    g_wohi[i] = __uint_as_float(hi);
    g_wolo[i] = __uint_as_float(lo);
}

// ============================================================
// Kernel 1: LayerNorm (writes hi/lo planes) + pair-bias.
// ============================================================
__global__ void ln_bias_kernel(const float* __restrict__ act,
                               const float* __restrict__ gamma,
                               const float* __restrict__ beta,
                               const float* __restrict__ wpb) {
    int warp = (blockIdx.x * blockDim.x + threadIdx.x) >> 5;
    int lane = threadIdx.x & 31;
    if (warp >= NN) return;
    const float4* a = (const float4*)(act + (size_t)warp * C);
    float4 v = a[lane];
    float s  = v.x + v.y + v.z + v.w;
    float s2 = v.x*v.x + v.y*v.y + v.z*v.z + v.w*v.w;
    #pragma unroll
    for (int o = 16; o > 0; o >>= 1) {
        s  += __shfl_xor_sync(0xffffffffu, s,  o);
        s2 += __shfl_xor_sync(0xffffffffu, s2, o);
    }
    float mu  = s * (1.0f / C);
    float var = s2 * (1.0f / C) - mu * mu;
    float r = rsqrtf(var + LN_EPS);
    float4 g = ((const float4*)gamma)[lane];
    float4 b = ((const float4*)beta)[lane];
    float4 o;
    o.x = (v.x - mu) * r * g.x + b.x;
    o.y = (v.y - mu) * r * g.y + b.y;
    o.z = (v.z - mu) * r * g.z + b.z;
    o.w = (v.w - mu) * r * g.w + b.w;
    float4 oh, ol;
    uint32_t th, tl;
    split_tf32(o.x, th, tl); oh.x = __uint_as_float(th); ol.x = __uint_as_float(tl);
    split_tf32(o.y, th, tl); oh.y = __uint_as_float(th); ol.y = __uint_as_float(tl);
    split_tf32(o.z, th, tl); oh.z = __uint_as_float(th); ol.z = __uint_as_float(tl);
    split_tf32(o.w, th, tl); oh.w = __uint_as_float(th); ol.w = __uint_as_float(tl);
    ((float4*)(g_xhi + (size_t)warp * C))[lane] = oh;
    ((float4*)(g_xlo + (size_t)warp * C))[lane] = ol;

    const float4* wb = (const float4*)(wpb + lane * 16);
    float4 w0 = wb[0], w1 = wb[1], w2 = wb[2], w3 = wb[3];
    float bh[4];
    bh[0] = o.x*w0.x + o.y*w1.x + o.z*w2.x + o.w*w3.x;
    bh[1] = o.x*w0.y + o.y*w1.y + o.z*w2.y + o.w*w3.y;
    bh[2] = o.x*w0.z + o.y*w1.z + o.z*w2.z + o.w*w3.z;
    bh[3] = o.x*w0.w + o.y*w1.w + o.z*w2.w + o.w*w3.w;
    #pragma unroll
    for (int h = 0; h < 4; h++) {
        #pragma unroll
        for (int off = 16; off > 0; off >>= 1)
            bh[h] += __shfl_xor_sync(0xffffffffu, bh[h], off);
    }
    if (lane == 0) {
        int qi = warp / NSEQ;
        int kj = warp - qi * NSEQ;
        #pragma unroll
        for (int h = 0; h < 4; h++)
            g_bias[h*NN + kj*NSEQ + qi] = bh[h];
    }
}

// ============================================================
// Kernel 2: projection GEMMs. Two-plane smem, BK=32, no in-loop splits.
// A stride 36 (addr≡4lr+lc, conflict-free), B stride 136 (≡8lc+lr).
// ============================================================
#define PA 36
#define PB 136

__global__ void __launch_bounds__(256, 2)
proj_mma() {
    __shared__ __align__(16) float Ahi[128*PA], Alo[128*PA];
    __shared__ __align__(16) float Bhi[32*PB],  Blo[32*PB];
    int op = blockIdx.x;
    const float* Whi = g_wsphi + op * C * C;
    const float* Wlo = g_wsplo + op * C * C;
    int bm = blockIdx.y * 128;
    int tid = threadIdx.x;
    int wid = tid >> 5, lane = tid & 31;
    int wm = (wid >> 2) * 64, wn = (wid & 3) * 32;
    int lr = lane >> 2, lc = lane & 3;

    float acc[4][4][4];
    #pragma unroll
    for (int mi = 0; mi < 4; mi++)
        #pragma unroll
        for (int ni = 0; ni < 4; ni++)
            #pragma unroll
            for (int e = 0; e < 4; e++) acc[mi][ni][e] = 0.0f;

    for (int k0 = 0; k0 < C; k0 += 32) {
        #pragma unroll
        for (int i = 0; i < 4; i++) {       // A: 128x32, both planes
            int e = i * 256 + tid;
            int r = e >> 3, c4 = (e & 7) * 4;
            *(float4*)&Ahi[r*PA + c4] = *(const float4*)(g_xhi + (size_t)(bm + r) * C + k0 + c4);
            *(float4*)&Alo[r*PA + c4] = *(const float4*)(g_xlo + (size_t)(bm + r) * C + k0 + c4);
        }
        #pragma unroll
        for (int i = 0; i < 4; i++) {       // B: 32x128, both planes
            int e = i * 256 + tid;
            int r = e >> 5, c4 = (e & 31) * 4;
            *(float4*)&Bhi[r*PB + c4] = *(const float4*)(Whi + (size_t)(k0 + r) * C + c4);
            *(float4*)&Blo[r*PB + c4] = *(const float4*)(Wlo + (size_t)(k0 + r) * C + c4);
        }
        __syncthreads();
        #pragma unroll
        for (int kc = 0; kc < 4; kc++) {
            int kb = kc * 8 + lc;
            uint32_t ahi[4][4], alo[4][4];
            #pragma unroll
            for (int mi = 0; mi < 4; mi++) {
                int r0 = wm + mi * 16 + lr;
                ahi[mi][0] = __float_as_uint(Ahi[r0*PA + kb]);
                ahi[mi][1] = __float_as_uint(Ahi[(r0+8)*PA + kb]);
                ahi[mi][2] = __float_as_uint(Ahi[r0*PA + kb + 4]);
                ahi[mi][3] = __float_as_uint(Ahi[(r0+8)*PA + kb + 4]);
                alo[mi][0] = __float_as_uint(Alo[r0*PA + kb]);
                alo[mi][1] = __float_as_uint(Alo[(r0+8)*PA + kb]);
                alo[mi][2] = __float_as_uint(Alo[r0*PA + kb + 4]);
                alo[mi][3] = __float_as_uint(Alo[(r0+8)*PA + kb + 4]);
            }
            uint32_t bhi[4][2], blo[4][2];
            #pragma unroll
            for (int ni = 0; ni < 4; ni++) {
                int n0 = wn + ni * 8 + lr;
                bhi[ni][0] = __float_as_uint(Bhi[kb*PB + n0]);
                bhi[ni][1] = __float_as_uint(Bhi[(kb+4)*PB + n0]);
                blo[ni][0] = __float_as_uint(Blo[kb*PB + n0]);
                blo[ni][1] = __float_as_uint(Blo[(kb+4)*PB + n0]);
            }
            #pragma unroll
            for (int mi = 0; mi < 4; mi++)
                #pragma unroll
                for (int ni = 0; ni < 4; ni++) {
                    mma8(acc[mi][ni], ahi[mi], bhi[ni]);
                    mma8(acc[mi][ni], ahi[mi], blo[ni]);
                    mma8(acc[mi][ni], alo[mi], bhi[ni]);
                }
        }
        __syncthreads();
    }

    const float qscale = 0.17677669529663687f;
    #pragma unroll
    for (int mi = 0; mi < 4; mi++) {
        #pragma unroll
        for (int ni = 0; ni < 4; ni++) {
            int row = bm + wm + mi * 16 + lr;
            int col = wn + ni * 8 + 2 * lc;
            float v0 = acc[mi][ni][0], v1 = acc[mi][ni][1];
            float v2 = acc[mi][ni][2], v3 = acc[mi][ni][3];
            size_t o0 = (size_t)row * C + col;
            size_t o1 = (size_t)(row + 8) * C + col;
            if (op == 0) {
                *(float2*)(g_q + o0) = make_float2(v0*qscale, v1*qscale);
                *(float2*)(g_q + o1) = make_float2(v2*qscale, v3*qscale);
            } else if (op == 3) {
                *(float2*)(g_gate + o0) = make_float2(1.0f/(1.0f+__expf(-v0)),
                                                      1.0f/(1.0f+__expf(-v1)));
                *(float2*)(g_gate + o1) = make_float2(1.0f/(1.0f+__expf(-v2)),
                                                      1.0f/(1.0f+__expf(-v3)));
            } else {
                float* dhi = (op == 1) ? g_khi : g_vhi;
                float* dlo = (op == 1) ? g_klo : g_vlo;
                uint32_t h0,l0,h1,l1,h2,l2,h3,l3;
                split_tf32(v0,h0,l0); split_tf32(v1,h1,l1);
                split_tf32(v2,h2,l2); split_tf32(v3,h3,l3);
                *(float2*)(dhi + o0) = make_float2(__uint_as_float(h0), __uint_as_float(h1));
                *(float2*)(dlo + o0) = make_float2(__uint_as_float(l0), __uint_as_float(l1));
                *(float2*)(dhi + o1) = make_float2(__uint_as_float(h2), __uint_as_float(h3));
                *(float2*)(dlo + o1) = make_float2(__uint_as_float(l2), __uint_as_float(l3));
            }
        }
    }
}

// ============================================================
// Kernel 3: tensor attention. One 320-thr block per (b,h), 10 warps.
// Two-plane K/V smem; bias direct to accumulator from L2.
// ============================================================
#define KC 16
#define VS 20
#define PS 20

__global__ void __launch_bounds__(320, 1)
attn_mma() {
    __shared__ __align__(16) float Khi[KC*36], Klo[KC*36];   // [key][d], stride 36
    __shared__ __align__(16) float Vthi[D*VS], Vtlo[D*VS];   // [d][key], stride 20
    __shared__ float Ps[10][32*PS];                           // per-warp P, stride 20
    __shared__ int idxs[KC];

    int b = blockIdx.x, h = blockIdx.y;
    int tid = threadIdx.x, wid = tid >> 5, lane = tid & 31;
    int lr = lane >> 2, lc = lane & 3;
    int cnt = g_cnt[b];
    const int* idxp = g_idx + b * NSEQ;
    const float* bhp = g_bias + (size_t)h * NN;
    int qbl = wid * 32;

    // Q fragments (split once per kernel)
    uint32_t qhi[2][4][4], qlo[2][4][4];
    {
        const float* qp = g_q + (size_t)(b * NSEQ) * C + h * D;
        #pragma unroll
        for (int mi = 0; mi < 2; mi++) {
            int r0 = qbl + mi * 16 + lr;
            #pragma unroll
            for (int kcc = 0; kcc < 4; kcc++) {
                int c0 = kcc * 8 + lc;
                split_tf32(qp[(size_t)r0 * C + c0],         qhi[mi][kcc][0], qlo[mi][kcc][0]);
                split_tf32(qp[(size_t)(r0 + 8) * C + c0],   qhi[mi][kcc][1], qlo[mi][kcc][1]);
                split_tf32(qp[(size_t)r0 * C + c0 + 4],     qhi[mi][kcc][2], qlo[mi][kcc][2]);
                split_tf32(qp[(size_t)(r0 + 8) * C + c0+4], qhi[mi][kcc][3], qlo[mi][kcc][3]);
            }
        }
    }

    float acc[2][4][4];
    #pragma unroll
    for (int mi = 0; mi < 2; mi++)
        #pragma unroll
        for (int ni = 0; ni < 4; ni++)
            #pragma unroll
            for (int e = 0; e < 4; e++) acc[mi][ni][e] = 0.0f;
    float lsum[2][2] = {{0.0f, 0.0f}, {0.0f, 0.0f}};

    int nch = (cnt + KC - 1) >> 4;
    for (int ch = 0; ch < nch; ch++) {
        int jc = ch << 4;
        __syncthreads();
        if (tid < KC) idxs[tid] = (jc + tid < cnt) ? idxp[jc + tid] : idxp[0];
        if (tid < 128) {
            int key = tid >> 3, dd = (tid & 7) * 4;
            int j = jc + key;
            int kg = (j < cnt) ? idxp[j] : idxp[0];
            size_t base = ((size_t)(b * NSEQ) + kg) * C + h * D + dd;
            *(float4*)&Khi[key*36 + dd] = *(const float4*)(g_khi + base);
            *(float4*)&Klo[key*36 + dd] = *(const float4*)(g_klo + base);
            float4 vh = *(const float4*)(g_vhi + base);
            float4 vl = *(const float4*)(g_vlo + base);
            Vthi[(dd+0)*VS + key] = vh.x; Vtlo[(dd+0)*VS + key] = vl.x;
            Vthi[(dd+1)*VS + key] = vh.y; Vtlo[(dd+1)*VS + key] = vl.y;
            Vthi[(dd+2)*VS + key] = vh.z; Vtlo[(dd+2)*VS + key] = vl.z;
            Vthi[(dd+3)*VS + key] = vh.w; Vtlo[(dd+3)*VS + key] = vl.w;
        }
        __syncthreads();

        // bias -> accumulator (pad keys -1e4 => exp -> exact 0)
        float sc[2][2][4];
        #pragma unroll
        for (int ni = 0; ni < 2; ni++) {
            int kl_ = ni * 8 + 2 * lc;
            bool ok0 = (jc + kl_ < cnt), ok1 = (jc + kl_ + 1 < cnt);
            int kg0 = idxs[kl_], kg1 = idxs[kl_ + 1];
            #pragma unroll
            for (int mi = 0; mi < 2; mi++) {
                int q0 = qbl + mi * 16 + lr;
                sc[mi][ni][0] = ok0 ? bhp[(size_t)kg0 * NSEQ + q0]     : -1e4f;
                sc[mi][ni][1] = ok1 ? bhp[(size_t)kg1 * NSEQ + q0]     : -1e4f;
                sc[mi][ni][2] = ok0 ? bhp[(size_t)kg0 * NSEQ + q0 + 8] : -1e4f;
                sc[mi][ni][3] = ok1 ? bhp[(size_t)kg1 * NSEQ + q0 + 8] : -1e4f;
            }
        }
        // S = Q K^T + bias
        #pragma unroll
        for (int kcc = 0; kcc < 4; kcc++) {
            int kb = kcc * 8 + lc;
            uint32_t bh2[2][2], bl2[2][2];
            #pragma unroll
            for (int ni = 0; ni < 2; ni++) {
                int n0 = ni * 8 + lr;
                bh2[ni][0] = __float_as_uint(Khi[n0*36 + kb]);
                bh2[ni][1] = __float_as_uint(Khi[n0*36 + kb + 4]);
                bl2[ni][0] = __float_as_uint(Klo[n0*36 + kb]);
                bl2[ni][1] = __float_as_uint(Klo[n0*36 + kb + 4]);
            }
            #pragma unroll
            for (int mi = 0; mi < 2; mi++)
                #pragma unroll
                for (int ni = 0; ni < 2; ni++) {
                    mma8(sc[mi][ni], qhi[mi][kcc], bh2[ni]);
                    mma8(sc[mi][ni], qhi[mi][kcc], bl2[ni]);
                    mma8(sc[mi][ni], qlo[mi][kcc], bh2[ni]);
                }
        }
        // exp + stash P
        #pragma unroll
        for (int mi = 0; mi < 2; mi++)
            #pragma unroll
            for (int ni = 0; ni < 2; ni++) {
                float p0 = __expf(sc[mi][ni][0]);
                float p1 = __expf(sc[mi][ni][1]);
                float p2 = __expf(sc[mi][ni][2]);
                float p3 = __expf(sc[mi][ni][3]);
                lsum[mi][0] += p0 + p1;
                lsum[mi][1] += p2 + p3;
                int r0 = mi * 16 + lr, cc = ni * 8 + 2 * lc;
                Ps[wid][r0*PS + cc] = p0;       Ps[wid][r0*PS + cc + 1] = p1;
                Ps[wid][(r0+8)*PS + cc] = p2;   Ps[wid][(r0+8)*PS + cc + 1] = p3;
            }
        __syncwarp();
        // O += P V
        #pragma unroll
        for (int kcc = 0; kcc < 2; kcc++) {
            int kb = kcc * 8 + lc;
            uint32_t phi[2][4], plo[2][4];
            #pragma unroll
            for (int mi = 0; mi < 2; mi++) {
                int r0 = mi * 16 + lr;
                split_tf32(Ps[wid][r0*PS + kb],         phi[mi][0], plo[mi][0]);
                split_tf32(Ps[wid][(r0+8)*PS + kb],     phi[mi][1], plo[mi][1]);
                split_tf32(Ps[wid][r0*PS + kb + 4],     phi[mi][2], plo[mi][2]);
                split_tf32(Ps[wid][(r0+8)*PS + kb + 4], phi[mi][3], plo[mi][3]);
            }
            #pragma unroll
            for (int ni = 0; ni < 4; ni++) {
                int n0 = ni * 8 + lr;
                uint32_t vh2[2] = { __float_as_uint(Vthi[n0*VS + kb]),
                                    __float_as_uint(Vthi[n0*VS + kb + 4]) };
                uint32_t vl2[2] = { __float_as_uint(Vtlo[n0*VS + kb]),
                                    __float_as_uint(Vtlo[n0*VS + kb + 4]) };
                #pragma unroll
                for (int mi = 0; mi < 2; mi++) {
                    mma8(acc[mi][ni], phi[mi], vh2);
                    mma8(acc[mi][ni], phi[mi], vl2);
                    mma8(acc[mi][ni], plo[mi], vh2);
                }
            }
        }
        __syncwarp();
    }

    // normalize + gate + write pre-split wa
    float inv[2][2];
    #pragma unroll
    for (int mi = 0; mi < 2; mi++)
        #pragma unroll
        for (int e = 0; e < 2; e++) {
            float lf = lsum[mi][e];
            lf += __shfl_xor_sync(0xffffffffu, lf, 1);
            lf += __shfl_xor_sync(0xffffffffu, lf, 2);
            inv[mi][e] = (lf > 0.0f) ? 1.0f / lf : 0.0f;
        }
    #pragma unroll
    for (int mi = 0; mi < 2; mi++) {
        int qg = b * NSEQ + qbl + mi * 16 + lr;
        #pragma unroll
        for (int ni = 0; ni < 4; ni++) {
            int dcol = h * D + ni * 8 + 2 * lc;
            size_t o0 = (size_t)qg * C + dcol;
            size_t o1 = o0 + (size_t)8 * C;
            float2 gt0 = *(const float2*)(g_gate + o0);
            float2 gt1 = *(const float2*)(g_gate + o1);
            float v0 = acc[mi][ni][0] * inv[mi][0] * gt0.x;
            float v1 = acc[mi][ni][1] * inv[mi][0] * gt0.y;
            float v2 = acc[mi][ni][2] * inv[mi][1] * gt1.x;
            float v3 = acc[mi][ni][3] * inv[mi][1] * gt1.y;
            uint32_t h0,l0,h1,l1,h2,l2,h3,l3;
            split_tf32(v0,h0,l0); split_tf32(v1,h1,l1);
            split_tf32(v2,h2,l2); split_tf32(v3,h3,l3);
            *(float2*)(g_wahi + o0) = make_float2(__uint_as_float(h0), __uint_as_float(h1));
            *(float2*)(g_walo + o0) = make_float2(__uint_as_float(l0), __uint_as_float(l1));
            *(float2*)(g_wahi + o1) = make_float2(__uint_as_float(h2), __uint_as_float(h3));
            *(float2*)(g_walo + o1) = make_float2(__uint_as_float(l2), __uint_as_float(l3));
        }
    }
}

// ============================================================
// Kernel 4: output GEMM. Two-plane smem, BK=32, B stored [n][k] stride 36.
// ============================================================
__global__ void __launch_bounds__(256, 2)
out_mma(float* __restrict__ out) {
    __shared__ __align__(16) float Ahi[128*PA], Alo[128*PA];
    __shared__ __align__(16) float Bhi[128*PA], Blo[128*PA];
    int bm = blockIdx.x * 128;
    int tid = threadIdx.x;
    int wid = tid >> 5, lane = tid & 31;
    int wm = (wid >> 2) * 64, wn = (wid & 3) * 32;
    int lr = lane >> 2, lc = lane & 3;

    float acc[4][4][4];
    #pragma unroll
    for (int mi = 0; mi < 4; mi++)
        #pragma unroll
        for (int ni = 0; ni < 4; ni++)
            #pragma unroll
            for (int e = 0; e < 4; e++) acc[mi][ni][e] = 0.0f;

    for (int k0 = 0; k0 < C; k0 += 32) {
        #pragma unroll
        for (int i = 0; i < 4; i++) {
            int e = i * 256 + tid;
            int r = e >> 3, c4 = (e & 7) * 4;
            *(float4*)&Ahi[r*PA + c4] = *(const float4*)(g_wahi + (size_t)(bm + r) * C + k0 + c4);
            *(float4*)&Alo[r*PA + c4] = *(const float4*)(g_walo + (size_t)(bm + r) * C + k0 + c4);
            *(float4*)&Bhi[r*PA + c4] = *(const float4*)(g_wohi + (size_t)r * C + k0 + c4);
            *(float4*)&Blo[r*PA + c4] = *(const float4*)(g_wolo + (size_t)r * C + k0 + c4);
        }
        __syncthreads();
        #pragma unroll
        for (int kc = 0; kc < 4; kc++) {
            int kb = kc * 8 + lc;
            uint32_t ahi[4][4], alo[4][4];
            #pragma unroll
            for (int mi = 0; mi < 4; mi++) {
                int r0 = wm + mi * 16 + lr;
                ahi[mi][0] = __float_as_uint(Ahi[r0*PA + kb]);
                ahi[mi][1] = __float_as_uint(Ahi[(r0+8)*PA + kb]);
                ahi[mi][2] = __float_as_uint(Ahi[r0*PA + kb + 4]);
                ahi[mi][3] = __float_as_uint(Ahi[(r0+8)*PA + kb + 4]);
                alo[mi][0] = __float_as_uint(Alo[r0*PA + kb]);
                alo[mi][1] = __float_as_uint(Alo[(r0+8)*PA + kb]);
                alo[mi][2] = __float_as_uint(Alo[r0*PA + kb + 4]);
                alo[mi][3] = __float_as_uint(Alo[(r0+8)*PA + kb + 4]);
            }
            uint32_t bhi[4][2], blo[4][2];
            #pragma unroll
            for (int ni = 0; ni < 4; ni++) {
                int n0 = wn + ni * 8 + lr;
                bhi[ni][0] = __float_as_uint(Bhi[n0*PA + kb]);
                bhi[ni][1] = __float_as_uint(Bhi[n0*PA + kb + 4]);
                blo[ni][0] = __float_as_uint(Blo[n0*PA + kb]);
                blo[ni][1] = __float_as_uint(Blo[n0*PA + kb + 4]);
            }
            #pragma unroll
            for (int mi = 0; mi < 4; mi++)
                #pragma unroll
                for (int ni = 0; ni < 4; ni++) {
                    mma8(acc[mi][ni], ahi[mi], bhi[ni]);
                    mma8(acc[mi][ni], ahi[mi], blo[ni]);
                    mma8(acc[mi][ni], alo[mi], bhi[ni]);
                }
        }
        __syncthreads();
    }

    #pragma unroll
    for (int mi = 0; mi < 4; mi++) {
        #pragma unroll
        for (int ni = 0; ni < 4; ni++) {
            int row = bm + wm + mi * 16 + lr;
            int col = wn + ni * 8 + 2 * lc;
            *(float2*)(out + (size_t)row * C + col)
                = make_float2(acc[mi][ni][0], acc[mi][ni][1]);
            *(float2*)(out + (size_t)(row+8) * C + col)
                = make_float2(acc[mi][ni][2], acc[mi][ni][3]);
        }
    }
}

// ============================================================
extern "C" void kernel_launch(void* const* d_in, const int* in_sizes, int n_in,
                              void* d_out, int out_size) {
    const float* act   = (const float*)d_in[0];
    const int*   pmask = (const int*)  d_in[1];
    const float* gamma = (const float*)d_in[2];
    const float* beta  = (const float*)d_in[3];
    const float* wpb   = (const float*)d_in[4];
    const float* wq    = (const float*)d_in[5];
    const float* wk    = (const float*)d_in[6];
    const float* wv    = (const float*)d_in[7];
    const float* wg    = (const float*)d_in[8];
    const float* wout  = (const float*)d_in[9];
    float* out = (float*)d_out;

    compact_kernel<<<NSEQ, NSEQ>>>(pmask);
    wsplit<<<(C*C + 255)/256, 256>>>(wq, wk, wv, wg, wout);
    ln_bias_kernel<<<NN/8, 256>>>(act, gamma, beta, wpb);
    proj_mma<<<dim3(4, NN/128), 256>>>();
    attn_mma<<<dim3(NSEQ, H), 320>>>();
    out_mma<<<NN/128, 256>>>(out);
}

// round 14
// speedup vs baseline: 1.3761x; 1.1440x over previous
#include <cuda_runtime.h>
#include <cuda_bf16.h>
#include <math.h>
#include <stdint.h>

#define NSEQ 320
#define C 128
#define CW 64            // packed bf16 words per row
#define H 4
#define D 32
#define NN (NSEQ*NSEQ)   // 102400
#define LN_EPS 1e-5f

// ---- scratch ----
__device__ uint32_t g_xh[NN*CW], g_xl[NN*CW];        // bf16 packed LN out
__device__ float    g_q[NN*C];
__device__ float    g_khi[NN*C], g_klo[NN*C];        // tf32 planes
__device__ float    g_vhi[NN*C], g_vlo[NN*C];
__device__ float    g_gate[NN*C];
__device__ float    g_wahi[NN*C], g_walo[NN*C];
__device__ float    g_bias[H*NN];                    // [h][k][q]
__device__ int      g_idx[NN];
__device__ int      g_cnt[NSEQ];
__device__ uint32_t g_wth[4*C*CW], g_wtl[4*C*CW];    // bf16 proj W, [op][n][kw]
__device__ float    g_wohi[C*C], g_wolo[C*C];        // tf32 wout planes [n][k]

// ---------- tf32 helpers ----------
__device__ __forceinline__ uint32_t tf32b(float x) {
    uint32_t u; asm("cvt.rna.tf32.f32 %0, %1;" : "=r"(u) : "f"(x)); return u;
}
__device__ __forceinline__ void split_tf32(float x, uint32_t& hi, uint32_t& lo) {
    hi = tf32b(x);
    lo = tf32b(x - __uint_as_float(hi));
}
__device__ __forceinline__ void mma8(float* d_, const uint32_t* a, const uint32_t* b) {
    asm volatile(
        "mma.sync.aligned.m16n8k8.row.col.f32.tf32.tf32.f32 "
        "{%0,%1,%2,%3}, {%4,%5,%6,%7}, {%8,%9}, {%0,%1,%2,%3};"
        : "+f"(d_[0]), "+f"(d_[1]), "+f"(d_[2]), "+f"(d_[3])
        : "r"(a[0]), "r"(a[1]), "r"(a[2]), "r"(a[3]), "r"(b[0]), "r"(b[1]));
}
// ---------- bf16 helpers ----------
__device__ __forceinline__ void split2(float x0, float x1, uint32_t& whi, uint32_t& wlo) {
    __nv_bfloat16 h0 = __float2bfloat16(x0);
    __nv_bfloat16 h1 = __float2bfloat16(x1);
    __nv_bfloat16 l0 = __float2bfloat16(x0 - __bfloat162float(h0));
    __nv_bfloat16 l1 = __float2bfloat16(x1 - __bfloat162float(h1));
    __nv_bfloat162 hh; hh.x = h0; hh.y = h1;
    __nv_bfloat162 ll; ll.x = l0; ll.y = l1;
    whi = *reinterpret_cast<uint32_t*>(&hh);
    wlo = *reinterpret_cast<uint32_t*>(&ll);
}
__device__ __forceinline__ void mma16(float* d_, const uint32_t* a, const uint32_t* b) {
    asm volatile(
        "mma.sync.aligned.m16n8k16.row.col.f32.bf16.bf16.f32 "
        "{%0,%1,%2,%3}, {%4,%5,%6,%7}, {%8,%9}, {%0,%1,%2,%3};"
        : "+f"(d_[0]), "+f"(d_[1]), "+f"(d_[2]), "+f"(d_[3])
        : "r"(a[0]), "r"(a[1]), "r"(a[2]), "r"(a[3]), "r"(b[0]), "r"(b[1]));
}

// ============================================================
// Kernel 0a: compaction of valid k columns per b.
// ============================================================
__global__ void compact_kernel(const int* __restrict__ pm) {
    int b = blockIdx.x;
    int t = threadIdx.x;
    __shared__ int wcnt[10], woff[10];
    int valid = (pm[(size_t)t * NSEQ + b] > 0) ? 1 : 0;
    unsigned ball = __ballot_sync(0xffffffffu, valid);
    int warp = t >> 5, lane = t & 31;
    if (lane == 0) wcnt[warp] = __popc(ball);
    __syncthreads();
    if (t == 0) {
        int s = 0;
        #pragma unroll
        for (int w = 0; w < 10; w++) { woff[w] = s; s += wcnt[w]; }
        g_cnt[b] = s;
    }
    __syncthreads();
    if (valid) {
        int pos = woff[warp] + __popc(ball & ((1u << lane) - 1u));
        g_idx[b * NSEQ + pos] = t;
    }
}

// ============================================================
// Kernel 0b: bf16 proj weights (transposed [n][kw]) + tf32 wout planes.
// ============================================================
__global__ void wsplit(const float* __restrict__ wq, const float* __restrict__ wk,
                       const float* __restrict__ wv, const float* __restrict__ wg,
                       const float* __restrict__ wout) {
    int i = blockIdx.x * 256 + threadIdx.x;   // 0..49151
    if (i < 4 * C * CW) {
        int op = i >> 13, rem = i & 8191;
        int n = rem >> 6, kw = rem & 63;
        const float* W = (op == 0) ? wq : (op == 1) ? wk : (op == 2) ? wv : wg;
        float v0 = W[(size_t)(2*kw) * C + n];
        float v1 = W[(size_t)(2*kw+1) * C + n];
        uint32_t wh, wl; split2(v0, v1, wh, wl);
        g_wth[i] = wh; g_wtl[i] = wl;
    } else if (i < 4 * C * CW + C * C) {
        int j = i - 4 * C * CW;               // flat [n][k]
        uint32_t hi, lo; split_tf32(wout[j], hi, lo);
        g_wohi[j] = __uint_as_float(hi);
        g_wolo[j] = __uint_as_float(lo);
    }
}

// ============================================================
// Kernel 1: LayerNorm (bf16 packed planes) + pair-bias.
// ============================================================
__global__ void ln_bias_kernel(const float* __restrict__ act,
                               const float* __restrict__ gamma,
                               const float* __restrict__ beta,
                               const float* __restrict__ wpb) {
    int warp = (blockIdx.x * blockDim.x + threadIdx.x) >> 5;
    int lane = threadIdx.x & 31;
    if (warp >= NN) return;
    const float4* a = (const float4*)(act + (size_t)warp * C);
    float4 v = a[lane];
    float s  = v.x + v.y + v.z + v.w;
    float s2 = v.x*v.x + v.y*v.y + v.z*v.z + v.w*v.w;
    #pragma unroll
    for (int o = 16; o > 0; o >>= 1) {
        s  += __shfl_xor_sync(0xffffffffu, s,  o);
        s2 += __shfl_xor_sync(0xffffffffu, s2, o);
    }
    float mu  = s * (1.0f / C);
    float var = s2 * (1.0f / C) - mu * mu;
    float r = rsqrtf(var + LN_EPS);
    float4 g = ((const float4*)gamma)[lane];
    float4 b = ((const float4*)beta)[lane];
    float4 o;
    o.x = (v.x - mu) * r * g.x + b.x;
    o.y = (v.y - mu) * r * g.y + b.y;
    o.z = (v.z - mu) * r * g.z + b.z;
    o.w = (v.w - mu) * r * g.w + b.w;
    uint32_t w0h, w0l, w1h, w1l;
    split2(o.x, o.y, w0h, w0l);
    split2(o.z, o.w, w1h, w1l);
    *(uint2*)(g_xh + (size_t)warp * CW + 2*lane) = make_uint2(w0h, w1h);
    *(uint2*)(g_xl + (size_t)warp * CW + 2*lane) = make_uint2(w0l, w1l);

    const float4* wb = (const float4*)(wpb + lane * 16);
    float4 w0 = wb[0], w1 = wb[1], w2 = wb[2], w3 = wb[3];
    float bh[4];
    bh[0] = o.x*w0.x + o.y*w1.x + o.z*w2.x + o.w*w3.x;
    bh[1] = o.x*w0.y + o.y*w1.y + o.z*w2.y + o.w*w3.y;
    bh[2] = o.x*w0.z + o.y*w1.z + o.z*w2.z + o.w*w3.z;
    bh[3] = o.x*w0.w + o.y*w1.w + o.z*w2.w + o.w*w3.w;
    #pragma unroll
    for (int h = 0; h < 4; h++) {
        #pragma unroll
        for (int off = 16; off > 0; off >>= 1)
            bh[h] += __shfl_xor_sync(0xffffffffu, bh[h], off);
    }
    if (lane == 0) {
        int qi = warp / NSEQ;
        int kj = warp - qi * NSEQ;
        #pragma unroll
        for (int h = 0; h < 4; h++)
            g_bias[h*NN + kj*NSEQ + qi] = bh[h];
    }
}

// ============================================================
// Kernel 2: projection GEMMs, bf16 3-term m16n8k16, BK=32 (16 words).
// Epilogue = R12 (K/V as tf32 float planes).
// ============================================================
#define SA 20

__global__ void __launch_bounds__(256, 2)
proj_mma() {
    __shared__ __align__(16) uint32_t Ah[128*SA], Al[128*SA];
    __shared__ __align__(16) uint32_t Bh[128*SA], Bl[128*SA];
    int op = blockIdx.x;
    const uint32_t* Wth = g_wth + op * C * CW;
    const uint32_t* Wtl = g_wtl + op * C * CW;
    int bm = blockIdx.y * 128;
    int tid = threadIdx.x;
    int wid = tid >> 5, lane = tid & 31;
    int wm = (wid >> 2) * 64, wn = (wid & 3) * 32;
    int lr = lane >> 2, lc = lane & 3;

    float acc[4][4][4];
    #pragma unroll
    for (int mi = 0; mi < 4; mi++)
        #pragma unroll
        for (int ni = 0; ni < 4; ni++)
            #pragma unroll
            for (int e = 0; e < 4; e++) acc[mi][ni][e] = 0.0f;

    for (int k0w = 0; k0w < CW; k0w += 16) {
        #pragma unroll
        for (int i = 0; i < 2; i++) {
            int e = i * 256 + tid;
            int r = e >> 2, q4 = (e & 3) * 4;
            *(uint4*)&Ah[r*SA + q4] = *(const uint4*)(g_xh + (size_t)(bm + r) * CW + k0w + q4);
            *(uint4*)&Al[r*SA + q4] = *(const uint4*)(g_xl + (size_t)(bm + r) * CW + k0w + q4);
            *(uint4*)&Bh[r*SA + q4] = *(const uint4*)(Wth + (size_t)r * CW + k0w + q4);
            *(uint4*)&Bl[r*SA + q4] = *(const uint4*)(Wtl + (size_t)r * CW + k0w + q4);
        }
        __syncthreads();
        #pragma unroll
        for (int kc = 0; kc < 2; kc++) {
            int wb = kc * 8;
            uint32_t ah[4][4], al[4][4];
            #pragma unroll
            for (int mi = 0; mi < 4; mi++) {
                int r0 = wm + mi * 16 + lr;
                ah[mi][0] = Ah[r0*SA + wb + lc];
                ah[mi][1] = Ah[(r0+8)*SA + wb + lc];
                ah[mi][2] = Ah[r0*SA + wb + lc + 4];
                ah[mi][3] = Ah[(r0+8)*SA + wb + lc + 4];
                al[mi][0] = Al[r0*SA + wb + lc];
                al[mi][1] = Al[(r0+8)*SA + wb + lc];
                al[mi][2] = Al[r0*SA + wb + lc + 4];
                al[mi][3] = Al[(r0+8)*SA + wb + lc + 4];
            }
            uint32_t bh2[4][2], bl2[4][2];
            #pragma unroll
            for (int ni = 0; ni < 4; ni++) {
                int n0 = wn + ni * 8 + lr;
                bh2[ni][0] = Bh[n0*SA + wb + lc];
                bh2[ni][1] = Bh[n0*SA + wb + lc + 4];
                bl2[ni][0] = Bl[n0*SA + wb + lc];
                bl2[ni][1] = Bl[n0*SA + wb + lc + 4];
            }
            #pragma unroll
            for (int mi = 0; mi < 4; mi++)
                #pragma unroll
                for (int ni = 0; ni < 4; ni++) {
                    mma16(acc[mi][ni], ah[mi], bh2[ni]);
                    mma16(acc[mi][ni], ah[mi], bl2[ni]);
                    mma16(acc[mi][ni], al[mi], bh2[ni]);
                }
        }
        __syncthreads();
    }

    const float qscale = 0.17677669529663687f;
    #pragma unroll
    for (int mi = 0; mi < 4; mi++) {
        #pragma unroll
        for (int ni = 0; ni < 4; ni++) {
            int row = bm + wm + mi * 16 + lr;
            int col = wn + ni * 8 + 2 * lc;
            float v0 = acc[mi][ni][0], v1 = acc[mi][ni][1];
            float v2 = acc[mi][ni][2], v3 = acc[mi][ni][3];
            size_t o0 = (size_t)row * C + col;
            size_t o1 = (size_t)(row + 8) * C + col;
            if (op == 0) {
                *(float2*)(g_q + o0) = make_float2(v0*qscale, v1*qscale);
                *(float2*)(g_q + o1) = make_float2(v2*qscale, v3*qscale);
            } else if (op == 3) {
                *(float2*)(g_gate + o0) = make_float2(1.0f/(1.0f+__expf(-v0)),
                                                      1.0f/(1.0f+__expf(-v1)));
                *(float2*)(g_gate + o1) = make_float2(1.0f/(1.0f+__expf(-v2)),
                                                      1.0f/(1.0f+__expf(-v3)));
            } else {
                float* dhi = (op == 1) ? g_khi : g_vhi;
                float* dlo = (op == 1) ? g_klo : g_vlo;
                uint32_t h0,l0,h1,l1,h2,l2,h3,l3;
                split_tf32(v0,h0,l0); split_tf32(v1,h1,l1);
                split_tf32(v2,h2,l2); split_tf32(v3,h3,l3);
                *(float2*)(dhi + o0) = make_float2(__uint_as_float(h0), __uint_as_float(h1));
                *(float2*)(dlo + o0) = make_float2(__uint_as_float(l0), __uint_as_float(l1));
                *(float2*)(dhi + o1) = make_float2(__uint_as_float(h2), __uint_as_float(h3));
                *(float2*)(dlo + o1) = make_float2(__uint_as_float(l2), __uint_as_float(l3));
            }
        }
    }
}

// ============================================================
// Kernel 3: tensor attention (R12 verbatim, tf32). One block per (b,h).
// ============================================================
#define KC 16
#define VS 20
#define PS 20

__global__ void __launch_bounds__(320, 1)
attn_mma() {
    __shared__ __align__(16) float Khi[KC*36], Klo[KC*36];
    __shared__ __align__(16) float Vthi[D*VS], Vtlo[D*VS];
    __shared__ float Ps[10][32*PS];
    __shared__ int idxs[KC];

    int b = blockIdx.x, h = blockIdx.y;
    int tid = threadIdx.x, wid = tid >> 5, lane = tid & 31;
    int lr = lane >> 2, lc = lane & 3;
    int cnt = g_cnt[b];
    const int* idxp = g_idx + b * NSEQ;
    const float* bhp = g_bias + (size_t)h * NN;
    int qbl = wid * 32;

    uint32_t qhi[2][4][4], qlo[2][4][4];
    {
        const float* qp = g_q + (size_t)(b * NSEQ) * C + h * D;
        #pragma unroll
        for (int mi = 0; mi < 2; mi++) {
            int r0 = qbl + mi * 16 + lr;
            #pragma unroll
            for (int kcc = 0; kcc < 4; kcc++) {
                int c0 = kcc * 8 + lc;
                split_tf32(qp[(size_t)r0 * C + c0],         qhi[mi][kcc][0], qlo[mi][kcc][0]);
                split_tf32(qp[(size_t)(r0 + 8) * C + c0],   qhi[mi][kcc][1], qlo[mi][kcc][1]);
                split_tf32(qp[(size_t)r0 * C + c0 + 4],     qhi[mi][kcc][2], qlo[mi][kcc][2]);
                split_tf32(qp[(size_t)(r0 + 8) * C + c0+4], qhi[mi][kcc][3], qlo[mi][kcc][3]);
            }
        }
    }

    float acc[2][4][4];
    #pragma unroll
    for (int mi = 0; mi < 2; mi++)
        #pragma unroll
        for (int ni = 0; ni < 4; ni++)
            #pragma unroll
            for (int e = 0; e < 4; e++) acc[mi][ni][e] = 0.0f;
    float lsum[2][2] = {{0.0f, 0.0f}, {0.0f, 0.0f}};

    int nch = (cnt + KC - 1) >> 4;
    for (int ch = 0; ch < nch; ch++) {
        int jc = ch << 4;
        __syncthreads();
        if (tid < KC) idxs[tid] = (jc + tid < cnt) ? idxp[jc + tid] : idxp[0];
        if (tid < 128) {
            int key = tid >> 3, dd = (tid & 7) * 4;
            int j = jc + key;
            int kg = (j < cnt) ? idxp[j] : idxp[0];
            size_t base = ((size_t)(b * NSEQ) + kg) * C + h * D + dd;
            *(float4*)&Khi[key*36 + dd] = *(const float4*)(g_khi + base);
            *(float4*)&Klo[key*36 + dd] = *(const float4*)(g_klo + base);
            float4 vh = *(const float4*)(g_vhi + base);
            float4 vl = *(const float4*)(g_vlo + base);
            Vthi[(dd+0)*VS + key] = vh.x; Vtlo[(dd+0)*VS + key] = vl.x;
            Vthi[(dd+1)*VS + key] = vh.y; Vtlo[(dd+1)*VS + key] = vl.y;
            Vthi[(dd+2)*VS + key] = vh.z; Vtlo[(dd+2)*VS + key] = vl.z;
            Vthi[(dd+3)*VS + key] = vh.w; Vtlo[(dd+3)*VS + key] = vl.w;
        }
        __syncthreads();

        float sc[2][2][4];
        #pragma unroll
        for (int ni = 0; ni < 2; ni++) {
            int kl_ = ni * 8 + 2 * lc;
            bool ok0 = (jc + kl_ < cnt), ok1 = (jc + kl_ + 1 < cnt);
            int kg0 = idxs[kl_], kg1 = idxs[kl_ + 1];
            #pragma unroll
            for (int mi = 0; mi < 2; mi++) {
                int q0 = qbl + mi * 16 + lr;
                sc[mi][ni][0] = ok0 ? bhp[(size_t)kg0 * NSEQ + q0]     : -1e4f;
                sc[mi][ni][1] = ok1 ? bhp[(size_t)kg1 * NSEQ + q0]     : -1e4f;
                sc[mi][ni][2] = ok0 ? bhp[(size_t)kg0 * NSEQ + q0 + 8] : -1e4f;
                sc[mi][ni][3] = ok1 ? bhp[(size_t)kg1 * NSEQ + q0 + 8] : -1e4f;
            }
        }
        #pragma unroll
        for (int kcc = 0; kcc < 4; kcc++) {
            int kb = kcc * 8 + lc;
            uint32_t bh2[2][2], bl2[2][2];
            #pragma unroll
            for (int ni = 0; ni < 2; ni++) {
                int n0 = ni * 8 + lr;
                bh2[ni][0] = __float_as_uint(Khi[n0*36 + kb]);
                bh2[ni][1] = __float_as_uint(Khi[n0*36 + kb + 4]);
                bl2[ni][0] = __float_as_uint(Klo[n0*36 + kb]);
                bl2[ni][1] = __float_as_uint(Klo[n0*36 + kb + 4]);
            }
            #pragma unroll
            for (int mi = 0; mi < 2; mi++)
                #pragma unroll
                for (int ni = 0; ni < 2; ni++) {
                    mma8(sc[mi][ni], qhi[mi][kcc], bh2[ni]);
                    mma8(sc[mi][ni], qhi[mi][kcc], bl2[ni]);
                    mma8(sc[mi][ni], qlo[mi][kcc], bh2[ni]);
                }
        }
        #pragma unroll
        for (int mi = 0; mi < 2; mi++)
            #pragma unroll
            for (int ni = 0; ni < 2; ni++) {
                float p0 = __expf(sc[mi][ni][0]);
                float p1 = __expf(sc[mi][ni][1]);
                float p2 = __expf(sc[mi][ni][2]);
                float p3 = __expf(sc[mi][ni][3]);
                lsum[mi][0] += p0 + p1;
                lsum[mi][1] += p2 + p3;
                int r0 = mi * 16 + lr, cc = ni * 8 + 2 * lc;
                Ps[wid][r0*PS + cc] = p0;       Ps[wid][r0*PS + cc + 1] = p1;
                Ps[wid][(r0+8)*PS + cc] = p2;   Ps[wid][(r0+8)*PS + cc + 1] = p3;
            }
        __syncwarp();
        #pragma unroll
        for (int kcc = 0; kcc < 2; kcc++) {
            int kb = kcc * 8 + lc;
            uint32_t phi[2][4], plo[2][4];
            #pragma unroll
            for (int mi = 0; mi < 2; mi++) {
                int r0 = mi * 16 + lr;
                split_tf32(Ps[wid][r0*PS + kb],         phi[mi][0], plo[mi][0]);
                split_tf32(Ps[wid][(r0+8)*PS + kb],     phi[mi][1], plo[mi][1]);
                split_tf32(Ps[wid][r0*PS + kb + 4],     phi[mi][2], plo[mi][2]);
                split_tf32(Ps[wid][(r0+8)*PS + kb + 4], phi[mi][3], plo[mi][3]);
            }
            #pragma unroll
            for (int ni = 0; ni < 4; ni++) {
                int n0 = ni * 8 + lr;
                uint32_t vh2[2] = { __float_as_uint(Vthi[n0*VS + kb]),
                                    __float_as_uint(Vthi[n0*VS + kb + 4]) };
                uint32_t vl2[2] = { __float_as_uint(Vtlo[n0*VS + kb]),
                                    __float_as_uint(Vtlo[n0*VS + kb + 4]) };
                #pragma unroll
                for (int mi = 0; mi < 2; mi++) {
                    mma8(acc[mi][ni], phi[mi], vh2);
                    mma8(acc[mi][ni], phi[mi], vl2);
                    mma8(acc[mi][ni], plo[mi], vh2);
                }
            }
        }
        __syncwarp();
    }

    float inv[2][2];
    #pragma unroll
    for (int mi = 0; mi < 2; mi++)
        #pragma unroll
        for (int e = 0; e < 2; e++) {
            float lf = lsum[mi][e];
            lf += __shfl_xor_sync(0xffffffffu, lf, 1);
            lf += __shfl_xor_sync(0xffffffffu, lf, 2);
            inv[mi][e] = (lf > 0.0f) ? 1.0f / lf : 0.0f;
        }
    #pragma unroll
    for (int mi = 0; mi < 2; mi++) {
        int qg = b * NSEQ + qbl + mi * 16 + lr;
        #pragma unroll
        for (int ni = 0; ni < 4; ni++) {
            int dcol = h * D + ni * 8 + 2 * lc;
            size_t o0 = (size_t)qg * C + dcol;
            size_t o1 = o0 + (size_t)8 * C;
            float2 gt0 = *(const float2*)(g_gate + o0);
            float2 gt1 = *(const float2*)(g_gate + o1);
            float v0 = acc[mi][ni][0] * inv[mi][0] * gt0.x;
            float v1 = acc[mi][ni][1] * inv[mi][0] * gt0.y;
            float v2 = acc[mi][ni][2] * inv[mi][1] * gt1.x;
            float v3 = acc[mi][ni][3] * inv[mi][1] * gt1.y;
            uint32_t h0,l0,h1,l1,h2,l2,h3,l3;
            split_tf32(v0,h0,l0); split_tf32(v1,h1,l1);
            split_tf32(v2,h2,l2); split_tf32(v3,h3,l3);
            *(float2*)(g_wahi + o0) = make_float2(__uint_as_float(h0), __uint_as_float(h1));
            *(float2*)(g_walo + o0) = make_float2(__uint_as_float(l0), __uint_as_float(l1));
            *(float2*)(g_wahi + o1) = make_float2(__uint_as_float(h2), __uint_as_float(h3));
            *(float2*)(g_walo + o1) = make_float2(__uint_as_float(l2), __uint_as_float(l3));
        }
    }
}

// ============================================================
// Kernel 4: output GEMM (R12 verbatim, tf32 two-plane, BK=32).
// ============================================================
#define PA 36

__global__ void __launch_bounds__(256, 2)
out_mma(float* __restrict__ out) {
    __shared__ __align__(16) float Ahi[128*PA], Alo[128*PA];
    __shared__ __align__(16) float Bhi[128*PA], Blo[128*PA];
    int bm = blockIdx.x * 128;
    int tid = threadIdx.x;
    int wid = tid >> 5, lane = tid & 31;
    int wm = (wid >> 2) * 64, wn = (wid & 3) * 32;
    int lr = lane >> 2, lc = lane & 3;

    float acc[4][4][4];
    #pragma unroll
    for (int mi = 0; mi < 4; mi++)
        #pragma unroll
        for (int ni = 0; ni < 4; ni++)
            #pragma unroll
            for (int e = 0; e < 4; e++) acc[mi][ni][e] = 0.0f;

    for (int k0 = 0; k0 < C; k0 += 32) {
        #pragma unroll
        for (int i = 0; i < 4; i++) {
            int e = i * 256 + tid;
            int r = e >> 3, c4 = (e & 7) * 4;
            *(float4*)&Ahi[r*PA + c4] = *(const float4*)(g_wahi + (size_t)(bm + r) * C + k0 + c4);
            *(float4*)&Alo[r*PA + c4] = *(const float4*)(g_walo + (size_t)(bm + r) * C + k0 + c4);
            *(float4*)&Bhi[r*PA + c4] = *(const float4*)(g_wohi + (size_t)r * C + k0 + c4);
            *(float4*)&Blo[r*PA + c4] = *(const float4*)(g_wolo + (size_t)r * C + k0 + c4);
        }
        __syncthreads();
        #pragma unroll
        for (int kc = 0; kc < 4; kc++) {
            int kb = kc * 8 + lc;
            uint32_t ahi[4][4], alo[4][4];
            #pragma unroll
            for (int mi = 0; mi < 4; mi++) {
                int r0 = wm + mi * 16 + lr;
                ahi[mi][0] = __float_as_uint(Ahi[r0*PA + kb]);
                ahi[mi][1] = __float_as_uint(Ahi[(r0+8)*PA + kb]);
                ahi[mi][2] = __float_as_uint(Ahi[r0*PA + kb + 4]);
                ahi[mi][3] = __float_as_uint(Ahi[(r0+8)*PA + kb + 4]);
                alo[mi][0] = __float_as_uint(Alo[r0*PA + kb]);
                alo[mi][1] = __float_as_uint(Alo[(r0+8)*PA + kb]);
                alo[mi][2] = __float_as_uint(Alo[r0*PA + kb + 4]);
                alo[mi][3] = __float_as_uint(Alo[(r0+8)*PA + kb + 4]);
            }
            uint32_t bhi[4][2], blo[4][2];
            #pragma unroll
            for (int ni = 0; ni < 4; ni++) {
                int n0 = wn + ni * 8 + lr;
                bhi[ni][0] = __float_as_uint(Bhi[n0*PA + kb]);
                bhi[ni][1] = __float_as_uint(Bhi[n0*PA + kb + 4]);
                blo[ni][0] = __float_as_uint(Blo[n0*PA + kb]);
                blo[ni][1] = __float_as_uint(Blo[n0*PA + kb + 4]);
            }
            #pragma unroll
            for (int mi = 0; mi < 4; mi++)
                #pragma unroll
                for (int ni = 0; ni < 4; ni++) {
                    mma8(acc[mi][ni], ahi[mi], bhi[ni]);
                    mma8(acc[mi][ni], ahi[mi], blo[ni]);
                    mma8(acc[mi][ni], alo[mi], bhi[ni]);
                }
        }
        __syncthreads();
    }

    #pragma unroll
    for (int mi = 0; mi < 4; mi++) {
        #pragma unroll
        for (int ni = 0; ni < 4; ni++) {
            int row = bm + wm + mi * 16 + lr;
            int col = wn + ni * 8 + 2 * lc;
            *(float2*)(out + (size_t)row * C + col)
                = make_float2(acc[mi][ni][0], acc[mi][ni][1]);
            *(float2*)(out + (size_t)(row+8) * C + col)
                = make_float2(acc[mi][ni][2], acc[mi][ni][3]);
        }
    }
}

// ============================================================
extern "C" void kernel_launch(void* const* d_in, const int* in_sizes, int n_in,
                              void* d_out, int out_size) {
    const float* act   = (const float*)d_in[0];
    const int*   pmask = (const int*)  d_in[1];
    const float* gamma = (const float*)d_in[2];
    const float* beta  = (const float*)d_in[3];
    const float* wpb   = (const float*)d_in[4];
    const float* wq    = (const float*)d_in[5];
    const float* wk    = (const float*)d_in[6];
    const float* wv    = (const float*)d_in[7];
    const float* wg    = (const float*)d_in[8];
    const float* wout  = (const float*)d_in[9];
    float* out = (float*)d_out;

    compact_kernel<<<NSEQ, NSEQ>>>(pmask);
    wsplit<<<192, 256>>>(wq, wk, wv, wg, wout);
    ln_bias_kernel<<<NN/8, 256>>>(act, gamma, beta, wpb);
    proj_mma<<<dim3(4, NN/128), 256>>>();
    attn_mma<<<dim3(NSEQ, H), 320>>>();
    out_mma<<<NN/128, 256>>>(out);
}

// round 15
// speedup vs baseline: 1.4343x; 1.0423x over previous
#include <cuda_runtime.h>
#include <cuda_bf16.h>
#include <math.h>
#include <stdint.h>

#define NSEQ 320
#define C 128
#define CW 64            // packed bf16 words per row
#define H 4
#define D 32
#define NN (NSEQ*NSEQ)   // 102400
#define LN_EPS 1e-5f

// ---- scratch ----
__device__ uint32_t g_xh[NN*CW], g_xl[NN*CW];        // bf16 packed LN out
__device__ float    g_q[NN*C];
__device__ float    g_khi[NN*C], g_klo[NN*C];        // tf32 planes (attention)
__device__ float    g_vhi[NN*C], g_vlo[NN*C];
__device__ float    g_gate[NN*C];
__device__ uint32_t g_wah[NN*CW], g_wal[NN*CW];      // bf16 packed attention out
__device__ float    g_bias[H*NN];                    // [h][k][q]
__device__ int      g_idx[NN];
__device__ int      g_cnt[NSEQ];
__device__ uint32_t g_wth[4*C*CW], g_wtl[4*C*CW];    // bf16 proj W, [op][n][kw]
__device__ uint32_t g_woth[C*CW], g_wotl[C*CW];      // bf16 wout, [n][kw]

// ---------- tf32 helpers ----------
__device__ __forceinline__ uint32_t tf32b(float x) {
    uint32_t u; asm("cvt.rna.tf32.f32 %0, %1;" : "=r"(u) : "f"(x)); return u;
}
__device__ __forceinline__ void split_tf32(float x, uint32_t& hi, uint32_t& lo) {
    hi = tf32b(x);
    lo = tf32b(x - __uint_as_float(hi));
}
__device__ __forceinline__ void mma8(float* d_, const uint32_t* a, const uint32_t* b) {
    asm volatile(
        "mma.sync.aligned.m16n8k8.row.col.f32.tf32.tf32.f32 "
        "{%0,%1,%2,%3}, {%4,%5,%6,%7}, {%8,%9}, {%0,%1,%2,%3};"
        : "+f"(d_[0]), "+f"(d_[1]), "+f"(d_[2]), "+f"(d_[3])
        : "r"(a[0]), "r"(a[1]), "r"(a[2]), "r"(a[3]), "r"(b[0]), "r"(b[1]));
}
// ---------- bf16 helpers ----------
__device__ __forceinline__ void split2(float x0, float x1, uint32_t& whi, uint32_t& wlo) {
    __nv_bfloat16 h0 = __float2bfloat16(x0);
    __nv_bfloat16 h1 = __float2bfloat16(x1);
    __nv_bfloat16 l0 = __float2bfloat16(x0 - __bfloat162float(h0));
    __nv_bfloat16 l1 = __float2bfloat16(x1 - __bfloat162float(h1));
    __nv_bfloat162 hh; hh.x = h0; hh.y = h1;
    __nv_bfloat162 ll; ll.x = l0; ll.y = l1;
    whi = *reinterpret_cast<uint32_t*>(&hh);
    wlo = *reinterpret_cast<uint32_t*>(&ll);
}
__device__ __forceinline__ void mma16(float* d_, const uint32_t* a, const uint32_t* b) {
    asm volatile(
        "mma.sync.aligned.m16n8k16.row.col.f32.bf16.bf16.f32 "
        "{%0,%1,%2,%3}, {%4,%5,%6,%7}, {%8,%9}, {%0,%1,%2,%3};"
        : "+f"(d_[0]), "+f"(d_[1]), "+f"(d_[2]), "+f"(d_[3])
        : "r"(a[0]), "r"(a[1]), "r"(a[2]), "r"(a[3]), "r"(b[0]), "r"(b[1]));
}

// ============================================================
// Kernel 0a: compaction of valid k columns per b.
// ============================================================
__global__ void compact_kernel(const int* __restrict__ pm) {
    int b = blockIdx.x;
    int t = threadIdx.x;
    __shared__ int wcnt[10], woff[10];
    int valid = (pm[(size_t)t * NSEQ + b] > 0) ? 1 : 0;
    unsigned ball = __ballot_sync(0xffffffffu, valid);
    int warp = t >> 5, lane = t & 31;
    if (lane == 0) wcnt[warp] = __popc(ball);
    __syncthreads();
    if (t == 0) {
        int s = 0;
        #pragma unroll
        for (int w = 0; w < 10; w++) { woff[w] = s; s += wcnt[w]; }
        g_cnt[b] = s;
    }
    __syncthreads();
    if (valid) {
        int pos = woff[warp] + __popc(ball & ((1u << lane) - 1u));
        g_idx[b * NSEQ + pos] = t;
    }
}

// ============================================================
// Kernel 0b: bf16 weights — proj + wout, both transposed [n][kw].
// ============================================================
__global__ void wsplit(const float* __restrict__ wq, const float* __restrict__ wk,
                       const float* __restrict__ wv, const float* __restrict__ wg,
                       const float* __restrict__ wout) {
    int i = blockIdx.x * 256 + threadIdx.x;   // 0..40959
    if (i < 4 * C * CW) {
        int op = i >> 13, rem = i & 8191;
        int n = rem >> 6, kw = rem & 63;
        const float* W = (op == 0) ? wq : (op == 1) ? wk : (op == 2) ? wv : wg;
        float v0 = W[(size_t)(2*kw) * C + n];
        float v1 = W[(size_t)(2*kw+1) * C + n];
        uint32_t wh, wl; split2(v0, v1, wh, wl);
        g_wth[i] = wh; g_wtl[i] = wl;
    } else if (i < 4 * C * CW + C * CW) {
        int j = i - 4 * C * CW;
        int n = j >> 6, kw = j & 63;
        // wout rows are [n][k] row-major: k already contiguous
        float v0 = wout[(size_t)n * C + 2*kw];
        float v1 = wout[(size_t)n * C + 2*kw + 1];
        uint32_t wh, wl; split2(v0, v1, wh, wl);
        g_woth[j] = wh; g_wotl[j] = wl;
    }
}

// ============================================================
// Kernel 1: LayerNorm (bf16 packed planes) + pair-bias.
// ============================================================
__global__ void ln_bias_kernel(const float* __restrict__ act,
                               const float* __restrict__ gamma,
                               const float* __restrict__ beta,
                               const float* __restrict__ wpb) {
    int warp = (blockIdx.x * blockDim.x + threadIdx.x) >> 5;
    int lane = threadIdx.x & 31;
    if (warp >= NN) return;
    const float4* a = (const float4*)(act + (size_t)warp * C);
    float4 v = a[lane];
    float s  = v.x + v.y + v.z + v.w;
    float s2 = v.x*v.x + v.y*v.y + v.z*v.z + v.w*v.w;
    #pragma unroll
    for (int o = 16; o > 0; o >>= 1) {
        s  += __shfl_xor_sync(0xffffffffu, s,  o);
        s2 += __shfl_xor_sync(0xffffffffu, s2, o);
    }
    float mu  = s * (1.0f / C);
    float var = s2 * (1.0f / C) - mu * mu;
    float r = rsqrtf(var + LN_EPS);
    float4 g = ((const float4*)gamma)[lane];
    float4 b = ((const float4*)beta)[lane];
    float4 o;
    o.x = (v.x - mu) * r * g.x + b.x;
    o.y = (v.y - mu) * r * g.y + b.y;
    o.z = (v.z - mu) * r * g.z + b.z;
    o.w = (v.w - mu) * r * g.w + b.w;
    uint32_t w0h, w0l, w1h, w1l;
    split2(o.x, o.y, w0h, w0l);
    split2(o.z, o.w, w1h, w1l);
    *(uint2*)(g_xh + (size_t)warp * CW + 2*lane) = make_uint2(w0h, w1h);
    *(uint2*)(g_xl + (size_t)warp * CW + 2*lane) = make_uint2(w0l, w1l);

    const float4* wb = (const float4*)(wpb + lane * 16);
    float4 w0 = wb[0], w1 = wb[1], w2 = wb[2], w3 = wb[3];
    float bh[4];
    bh[0] = o.x*w0.x + o.y*w1.x + o.z*w2.x + o.w*w3.x;
    bh[1] = o.x*w0.y + o.y*w1.y + o.z*w2.y + o.w*w3.y;
    bh[2] = o.x*w0.z + o.y*w1.z + o.z*w2.z + o.w*w3.z;
    bh[3] = o.x*w0.w + o.y*w1.w + o.z*w2.w + o.w*w3.w;
    #pragma unroll
    for (int h = 0; h < 4; h++) {
        #pragma unroll
        for (int off = 16; off > 0; off >>= 1)
            bh[h] += __shfl_xor_sync(0xffffffffu, bh[h], off);
    }
    if (lane == 0) {
        int qi = warp / NSEQ;
        int kj = warp - qi * NSEQ;
        #pragma unroll
        for (int h = 0; h < 4; h++)
            g_bias[h*NN + kj*NSEQ + qi] = bh[h];
    }
}

// ============================================================
// Kernel 2: projection GEMMs, bf16 3-term m16n8k16 (R14 verbatim).
// ============================================================
#define SA 20

__global__ void __launch_bounds__(256, 2)
proj_mma() {
    __shared__ __align__(16) uint32_t Ah[128*SA], Al[128*SA];
    __shared__ __align__(16) uint32_t Bh[128*SA], Bl[128*SA];
    int op = blockIdx.x;
    const uint32_t* Wth = g_wth + op * C * CW;
    const uint32_t* Wtl = g_wtl + op * C * CW;
    int bm = blockIdx.y * 128;
    int tid = threadIdx.x;
    int wid = tid >> 5, lane = tid & 31;
    int wm = (wid >> 2) * 64, wn = (wid & 3) * 32;
    int lr = lane >> 2, lc = lane & 3;

    float acc[4][4][4];
    #pragma unroll
    for (int mi = 0; mi < 4; mi++)
        #pragma unroll
        for (int ni = 0; ni < 4; ni++)
            #pragma unroll
            for (int e = 0; e < 4; e++) acc[mi][ni][e] = 0.0f;

    for (int k0w = 0; k0w < CW; k0w += 16) {
        #pragma unroll
        for (int i = 0; i < 2; i++) {
            int e = i * 256 + tid;
            int r = e >> 2, q4 = (e & 3) * 4;
            *(uint4*)&Ah[r*SA + q4] = *(const uint4*)(g_xh + (size_t)(bm + r) * CW + k0w + q4);
            *(uint4*)&Al[r*SA + q4] = *(const uint4*)(g_xl + (size_t)(bm + r) * CW + k0w + q4);
            *(uint4*)&Bh[r*SA + q4] = *(const uint4*)(Wth + (size_t)r * CW + k0w + q4);
            *(uint4*)&Bl[r*SA + q4] = *(const uint4*)(Wtl + (size_t)r * CW + k0w + q4);
        }
        __syncthreads();
        #pragma unroll
        for (int kc = 0; kc < 2; kc++) {
            int wb = kc * 8;
            uint32_t ah[4][4], al[4][4];
            #pragma unroll
            for (int mi = 0; mi < 4; mi++) {
                int r0 = wm + mi * 16 + lr;
                ah[mi][0] = Ah[r0*SA + wb + lc];
                ah[mi][1] = Ah[(r0+8)*SA + wb + lc];
                ah[mi][2] = Ah[r0*SA + wb + lc + 4];
                ah[mi][3] = Ah[(r0+8)*SA + wb + lc + 4];
                al[mi][0] = Al[r0*SA + wb + lc];
                al[mi][1] = Al[(r0+8)*SA + wb + lc];
                al[mi][2] = Al[r0*SA + wb + lc + 4];
                al[mi][3] = Al[(r0+8)*SA + wb + lc + 4];
            }
            uint32_t bh2[4][2], bl2[4][2];
            #pragma unroll
            for (int ni = 0; ni < 4; ni++) {
                int n0 = wn + ni * 8 + lr;
                bh2[ni][0] = Bh[n0*SA + wb + lc];
                bh2[ni][1] = Bh[n0*SA + wb + lc + 4];
                bl2[ni][0] = Bl[n0*SA + wb + lc];
                bl2[ni][1] = Bl[n0*SA + wb + lc + 4];
            }
            #pragma unroll
            for (int mi = 0; mi < 4; mi++)
                #pragma unroll
                for (int ni = 0; ni < 4; ni++) {
                    mma16(acc[mi][ni], ah[mi], bh2[ni]);
                    mma16(acc[mi][ni], ah[mi], bl2[ni]);
                    mma16(acc[mi][ni], al[mi], bh2[ni]);
                }
        }
        __syncthreads();
    }

    const float qscale = 0.17677669529663687f;
    #pragma unroll
    for (int mi = 0; mi < 4; mi++) {
        #pragma unroll
        for (int ni = 0; ni < 4; ni++) {
            int row = bm + wm + mi * 16 + lr;
            int col = wn + ni * 8 + 2 * lc;
            float v0 = acc[mi][ni][0], v1 = acc[mi][ni][1];
            float v2 = acc[mi][ni][2], v3 = acc[mi][ni][3];
            size_t o0 = (size_t)row * C + col;
            size_t o1 = (size_t)(row + 8) * C + col;
            if (op == 0) {
                *(float2*)(g_q + o0) = make_float2(v0*qscale, v1*qscale);
                *(float2*)(g_q + o1) = make_float2(v2*qscale, v3*qscale);
            } else if (op == 3) {
                *(float2*)(g_gate + o0) = make_float2(1.0f/(1.0f+__expf(-v0)),
                                                      1.0f/(1.0f+__expf(-v1)));
                *(float2*)(g_gate + o1) = make_float2(1.0f/(1.0f+__expf(-v2)),
                                                      1.0f/(1.0f+__expf(-v3)));
            } else {
                float* dhi = (op == 1) ? g_khi : g_vhi;
                float* dlo = (op == 1) ? g_klo : g_vlo;
                uint32_t h0,l0,h1,l1,h2,l2,h3,l3;
                split_tf32(v0,h0,l0); split_tf32(v1,h1,l1);
                split_tf32(v2,h2,l2); split_tf32(v3,h3,l3);
                *(float2*)(dhi + o0) = make_float2(__uint_as_float(h0), __uint_as_float(h1));
                *(float2*)(dlo + o0) = make_float2(__uint_as_float(l0), __uint_as_float(l1));
                *(float2*)(dhi + o1) = make_float2(__uint_as_float(h2), __uint_as_float(h3));
                *(float2*)(dlo + o1) = make_float2(__uint_as_float(l2), __uint_as_float(l3));
            }
        }
    }
}

// ============================================================
// Kernel 3: tensor attention (tf32, R12-proven), bf16 wa epilogue.
// ============================================================
#define KC 16
#define VS 20
#define PS 20

__global__ void __launch_bounds__(320, 1)
attn_mma() {
    __shared__ __align__(16) float Khi[KC*36], Klo[KC*36];
    __shared__ __align__(16) float Vthi[D*VS], Vtlo[D*VS];
    __shared__ float Ps[10][32*PS];
    __shared__ int idxs[KC];

    int b = blockIdx.x, h = blockIdx.y;
    int tid = threadIdx.x, wid = tid >> 5, lane = tid & 31;
    int lr = lane >> 2, lc = lane & 3;
    int cnt = g_cnt[b];
    const int* idxp = g_idx + b * NSEQ;
    const float* bhp = g_bias + (size_t)h * NN;
    int qbl = wid * 32;

    uint32_t qhi[2][4][4], qlo[2][4][4];
    {
        const float* qp = g_q + (size_t)(b * NSEQ) * C + h * D;
        #pragma unroll
        for (int mi = 0; mi < 2; mi++) {
            int r0 = qbl + mi * 16 + lr;
            #pragma unroll
            for (int kcc = 0; kcc < 4; kcc++) {
                int c0 = kcc * 8 + lc;
                split_tf32(qp[(size_t)r0 * C + c0],         qhi[mi][kcc][0], qlo[mi][kcc][0]);
                split_tf32(qp[(size_t)(r0 + 8) * C + c0],   qhi[mi][kcc][1], qlo[mi][kcc][1]);
                split_tf32(qp[(size_t)r0 * C + c0 + 4],     qhi[mi][kcc][2], qlo[mi][kcc][2]);
                split_tf32(qp[(size_t)(r0 + 8) * C + c0+4], qhi[mi][kcc][3], qlo[mi][kcc][3]);
            }
        }
    }

    float acc[2][4][4];
    #pragma unroll
    for (int mi = 0; mi < 2; mi++)
        #pragma unroll
        for (int ni = 0; ni < 4; ni++)
            #pragma unroll
            for (int e = 0; e < 4; e++) acc[mi][ni][e] = 0.0f;
    float lsum[2][2] = {{0.0f, 0.0f}, {0.0f, 0.0f}};

    int nch = (cnt + KC - 1) >> 4;
    for (int ch = 0; ch < nch; ch++) {
        int jc = ch << 4;
        __syncthreads();
        if (tid < KC) idxs[tid] = (jc + tid < cnt) ? idxp[jc + tid] : idxp[0];
        if (tid < 128) {
            int key = tid >> 3, dd = (tid & 7) * 4;
            int j = jc + key;
            int kg = (j < cnt) ? idxp[j] : idxp[0];
            size_t base = ((size_t)(b * NSEQ) + kg) * C + h * D + dd;
            *(float4*)&Khi[key*36 + dd] = *(const float4*)(g_khi + base);
            *(float4*)&Klo[key*36 + dd] = *(const float4*)(g_klo + base);
            float4 vh = *(const float4*)(g_vhi + base);
            float4 vl = *(const float4*)(g_vlo + base);
            Vthi[(dd+0)*VS + key] = vh.x; Vtlo[(dd+0)*VS + key] = vl.x;
            Vthi[(dd+1)*VS + key] = vh.y; Vtlo[(dd+1)*VS + key] = vl.y;
            Vthi[(dd+2)*VS + key] = vh.z; Vtlo[(dd+2)*VS + key] = vl.z;
            Vthi[(dd+3)*VS + key] = vh.w; Vtlo[(dd+3)*VS + key] = vl.w;
        }
        __syncthreads();

        float sc[2][2][4];
        #pragma unroll
        for (int ni = 0; ni < 2; ni++) {
            int kl_ = ni * 8 + 2 * lc;
            bool ok0 = (jc + kl_ < cnt), ok1 = (jc + kl_ + 1 < cnt);
            int kg0 = idxs[kl_], kg1 = idxs[kl_ + 1];
            #pragma unroll
            for (int mi = 0; mi < 2; mi++) {
                int q0 = qbl + mi * 16 + lr;
                sc[mi][ni][0] = ok0 ? bhp[(size_t)kg0 * NSEQ + q0]     : -1e4f;
                sc[mi][ni][1] = ok1 ? bhp[(size_t)kg1 * NSEQ + q0]     : -1e4f;
                sc[mi][ni][2] = ok0 ? bhp[(size_t)kg0 * NSEQ + q0 + 8] : -1e4f;
                sc[mi][ni][3] = ok1 ? bhp[(size_t)kg1 * NSEQ + q0 + 8] : -1e4f;
            }
        }
        #pragma unroll
        for (int kcc = 0; kcc < 4; kcc++) {
            int kb = kcc * 8 + lc;
            uint32_t bh2[2][2], bl2[2][2];
            #pragma unroll
            for (int ni = 0; ni < 2; ni++) {
                int n0 = ni * 8 + lr;
                bh2[ni][0] = __float_as_uint(Khi[n0*36 + kb]);
                bh2[ni][1] = __float_as_uint(Khi[n0*36 + kb + 4]);
                bl2[ni][0] = __float_as_uint(Klo[n0*36 + kb]);
                bl2[ni][1] = __float_as_uint(Klo[n0*36 + kb + 4]);
            }
            #pragma unroll
            for (int mi = 0; mi < 2; mi++)
                #pragma unroll
                for (int ni = 0; ni < 2; ni++) {
                    mma8(sc[mi][ni], qhi[mi][kcc], bh2[ni]);
                    mma8(sc[mi][ni], qhi[mi][kcc], bl2[ni]);
                    mma8(sc[mi][ni], qlo[mi][kcc], bh2[ni]);
                }
        }
        #pragma unroll
        for (int mi = 0; mi < 2; mi++)
            #pragma unroll
            for (int ni = 0; ni < 2; ni++) {
                float p0 = __expf(sc[mi][ni][0]);
                float p1 = __expf(sc[mi][ni][1]);
                float p2 = __expf(sc[mi][ni][2]);
                float p3 = __expf(sc[mi][ni][3]);
                lsum[mi][0] += p0 + p1;
                lsum[mi][1] += p2 + p3;
                int r0 = mi * 16 + lr, cc = ni * 8 + 2 * lc;
                Ps[wid][r0*PS + cc] = p0;       Ps[wid][r0*PS + cc + 1] = p1;
                Ps[wid][(r0+8)*PS + cc] = p2;   Ps[wid][(r0+8)*PS + cc + 1] = p3;
            }
        __syncwarp();
        #pragma unroll
        for (int kcc = 0; kcc < 2; kcc++) {
            int kb = kcc * 8 + lc;
            uint32_t phi[2][4], plo[2][4];
            #pragma unroll
            for (int mi = 0; mi < 2; mi++) {
                int r0 = mi * 16 + lr;
                split_tf32(Ps[wid][r0*PS + kb],         phi[mi][0], plo[mi][0]);
                split_tf32(Ps[wid][(r0+8)*PS + kb],     phi[mi][1], plo[mi][1]);
                split_tf32(Ps[wid][r0*PS + kb + 4],     phi[mi][2], plo[mi][2]);
                split_tf32(Ps[wid][(r0+8)*PS + kb + 4], phi[mi][3], plo[mi][3]);
            }
            #pragma unroll
            for (int ni = 0; ni < 4; ni++) {
                int n0 = ni * 8 + lr;
                uint32_t vh2[2] = { __float_as_uint(Vthi[n0*VS + kb]),
                                    __float_as_uint(Vthi[n0*VS + kb + 4]) };
                uint32_t vl2[2] = { __float_as_uint(Vtlo[n0*VS + kb]),
                                    __float_as_uint(Vtlo[n0*VS + kb + 4]) };
                #pragma unroll
                for (int mi = 0; mi < 2; mi++) {
                    mma8(acc[mi][ni], phi[mi], vh2);
                    mma8(acc[mi][ni], phi[mi], vl2);
                    mma8(acc[mi][ni], plo[mi], vh2);
                }
            }
        }
        __syncwarp();
    }

    float inv[2][2];
    #pragma unroll
    for (int mi = 0; mi < 2; mi++)
        #pragma unroll
        for (int e = 0; e < 2; e++) {
            float lf = lsum[mi][e];
            lf += __shfl_xor_sync(0xffffffffu, lf, 1);
            lf += __shfl_xor_sync(0xffffffffu, lf, 2);
            inv[mi][e] = (lf > 0.0f) ? 1.0f / lf : 0.0f;
        }
    #pragma unroll
    for (int mi = 0; mi < 2; mi++) {
        int qg = b * NSEQ + qbl + mi * 16 + lr;
        #pragma unroll
        for (int ni = 0; ni < 4; ni++) {
            int dcol = h * D + ni * 8 + 2 * lc;
            size_t o0 = (size_t)qg * C + dcol;
            size_t o1 = o0 + (size_t)8 * C;
            float2 gt0 = *(const float2*)(g_gate + o0);
            float2 gt1 = *(const float2*)(g_gate + o1);
            float v0 = acc[mi][ni][0] * inv[mi][0] * gt0.x;
            float v1 = acc[mi][ni][1] * inv[mi][0] * gt0.y;
            float v2 = acc[mi][ni][2] * inv[mi][1] * gt1.x;
            float v3 = acc[mi][ni][3] * inv[mi][1] * gt1.y;
            int wc = dcol >> 1;
            uint32_t wh, wl;
            split2(v0, v1, wh, wl);
            g_wah[(size_t)qg * CW + wc] = wh;
            g_wal[(size_t)qg * CW + wc] = wl;
            split2(v2, v3, wh, wl);
            g_wah[(size_t)(qg + 8) * CW + wc] = wh;
            g_wal[(size_t)(qg + 8) * CW + wc] = wl;
        }
    }
}

// ============================================================
// Kernel 4: output GEMM, bf16 3-term (clone of proj_mma inner loop).
// ============================================================
__global__ void __launch_bounds__(256, 2)
out_mma(float* __restrict__ out) {
    __shared__ __align__(16) uint32_t Ah[128*SA], Al[128*SA];
    __shared__ __align__(16) uint32_t Bh[128*SA], Bl[128*SA];
    int bm = blockIdx.x * 128;
    int tid = threadIdx.x;
    int wid = tid >> 5, lane = tid & 31;
    int wm = (wid >> 2) * 64, wn = (wid & 3) * 32;
    int lr = lane >> 2, lc = lane & 3;

    float acc[4][4][4];
    #pragma unroll
    for (int mi = 0; mi < 4; mi++)
        #pragma unroll
        for (int ni = 0; ni < 4; ni++)
            #pragma unroll
            for (int e = 0; e < 4; e++) acc[mi][ni][e] = 0.0f;

    for (int k0w = 0; k0w < CW; k0w += 16) {
        #pragma unroll
        for (int i = 0; i < 2; i++) {
            int e = i * 256 + tid;
            int r = e >> 2, q4 = (e & 3) * 4;
            *(uint4*)&Ah[r*SA + q4] = *(const uint4*)(g_wah + (size_t)(bm + r) * CW + k0w + q4);
            *(uint4*)&Al[r*SA + q4] = *(const uint4*)(g_wal + (size_t)(bm + r) * CW + k0w + q4);
            *(uint4*)&Bh[r*SA + q4] = *(const uint4*)(g_woth + (size_t)r * CW + k0w + q4);
            *(uint4*)&Bl[r*SA + q4] = *(const uint4*)(g_wotl + (size_t)r * CW + k0w + q4);
        }
        __syncthreads();
        #pragma unroll
        for (int kc = 0; kc < 2; kc++) {
            int wb = kc * 8;
            uint32_t ah[4][4], al[4][4];
            #pragma unroll
            for (int mi = 0; mi < 4; mi++) {
                int r0 = wm + mi * 16 + lr;
                ah[mi][0] = Ah[r0*SA + wb + lc];
                ah[mi][1] = Ah[(r0+8)*SA + wb + lc];
                ah[mi][2] = Ah[r0*SA + wb + lc + 4];
                ah[mi][3] = Ah[(r0+8)*SA + wb + lc + 4];
                al[mi][0] = Al[r0*SA + wb + lc];
                al[mi][1] = Al[(r0+8)*SA + wb + lc];
                al[mi][2] = Al[r0*SA + wb + lc + 4];
                al[mi][3] = Al[(r0+8)*SA + wb + lc + 4];
            }
            uint32_t bh2[4][2], bl2[4][2];
            #pragma unroll
            for (int ni = 0; ni < 4; ni++) {
                int n0 = wn + ni * 8 + lr;
                bh2[ni][0] = Bh[n0*SA + wb + lc];
                bh2[ni][1] = Bh[n0*SA + wb + lc + 4];
                bl2[ni][0] = Bl[n0*SA + wb + lc];
                bl2[ni][1] = Bl[n0*SA + wb + lc + 4];
            }
            #pragma unroll
            for (int mi = 0; mi < 4; mi++)
                #pragma unroll
                for (int ni = 0; ni < 4; ni++) {
                    mma16(acc[mi][ni], ah[mi], bh2[ni]);
                    mma16(acc[mi][ni], ah[mi], bl2[ni]);
                    mma16(acc[mi][ni], al[mi], bh2[ni]);
                }
        }
        __syncthreads();
    }

    #pragma unroll
    for (int mi = 0; mi < 4; mi++) {
        #pragma unroll
        for (int ni = 0; ni < 4; ni++) {
            int row = bm + wm + mi * 16 + lr;
            int col = wn + ni * 8 + 2 * lc;
            *(float2*)(out + (size_t)row * C + col)
                = make_float2(acc[mi][ni][0], acc[mi][ni][1]);
            *(float2*)(out + (size_t)(row+8) * C + col)
                = make_float2(acc[mi][ni][2], acc[mi][ni][3]);
        }
    }
}

// ============================================================
extern "C" void kernel_launch(void* const* d_in, const int* in_sizes, int n_in,
                              void* d_out, int out_size) {
    const float* act   = (const float*)d_in[0];
    const int*   pmask = (const int*)  d_in[1];
    const float* gamma = (const float*)d_in[2];
    const float* beta  = (const float*)d_in[3];
    const float* wpb   = (const float*)d_in[4];
    const float* wq    = (const float*)d_in[5];
    const float* wk    = (const float*)d_in[6];
    const float* wv    = (const float*)d_in[7];
    const float* wg    = (const float*)d_in[8];
    const float* wout  = (const float*)d_in[9];
    float* out = (float*)d_out;

    compact_kernel<<<NSEQ, NSEQ>>>(pmask);
    wsplit<<<160, 256>>>(wq, wk, wv, wg, wout);
    ln_bias_kernel<<<NN/8, 256>>>(act, gamma, beta, wpb);
    proj_mma<<<dim3(4, NN/128), 256>>>();
    attn_mma<<<dim3(NSEQ, H), 320>>>();
    out_mma<<<NN/128, 256>>>(out);
}

// round 17
// speedup vs baseline: 1.5783x; 1.1004x over previous
#include <cuda_runtime.h>
#include <cuda_bf16.h>
#include <math.h>
#include <stdint.h>

#define NSEQ 320
#define C 128
#define CW 64            // packed bf16 words per row
#define H 4
#define D 32
#define NN (NSEQ*NSEQ)   // 102400
#define LN_EPS 1e-5f

// ---- scratch ----
__device__ uint32_t g_xh[NN*CW], g_xl[NN*CW];        // bf16 packed LN out
__device__ float    g_q[NN*C];
__device__ float    g_khi[NN*C], g_klo[NN*C];        // tf32 planes (attention)
__device__ float    g_vhi[NN*C], g_vlo[NN*C];
__device__ float    g_gate[NN*C];
__device__ uint32_t g_wah[NN*CW], g_wal[NN*CW];      // bf16 packed attention out
__device__ float    g_bias[H*NN];                    // [h][k][q]
__device__ int      g_idx[NN];
__device__ int      g_cnt[NSEQ];
__device__ uint32_t g_wth[4*C*CW], g_wtl[4*C*CW];    // bf16 proj W, [op][n][kw]
__device__ uint32_t g_woth[C*CW], g_wotl[C*CW];      // bf16 wout, [n][kw]

// ---------- tf32 helpers ----------
__device__ __forceinline__ uint32_t tf32b(float x) {
    uint32_t u; asm("cvt.rna.tf32.f32 %0, %1;" : "=r"(u) : "f"(x)); return u;
}
__device__ __forceinline__ void split_tf32(float x, uint32_t& hi, uint32_t& lo) {
    hi = tf32b(x);
    lo = tf32b(x - __uint_as_float(hi));
}
__device__ __forceinline__ void mma8(float* d_, const uint32_t* a, const uint32_t* b) {
    asm volatile(
        "mma.sync.aligned.m16n8k8.row.col.f32.tf32.tf32.f32 "
        "{%0,%1,%2,%3}, {%4,%5,%6,%7}, {%8,%9}, {%0,%1,%2,%3};"
        : "+f"(d_[0]), "+f"(d_[1]), "+f"(d_[2]), "+f"(d_[3])
        : "r"(a[0]), "r"(a[1]), "r"(a[2]), "r"(a[3]), "r"(b[0]), "r"(b[1]));
}
// ---------- bf16 helpers ----------
__device__ __forceinline__ void split2(float x0, float x1, uint32_t& whi, uint32_t& wlo) {
    __nv_bfloat16 h0 = __float2bfloat16(x0);
    __nv_bfloat16 h1 = __float2bfloat16(x1);
    __nv_bfloat16 l0 = __float2bfloat16(x0 - __bfloat162float(h0));
    __nv_bfloat16 l1 = __float2bfloat16(x1 - __bfloat162float(h1));
    __nv_bfloat162 hh; hh.x = h0; hh.y = h1;
    __nv_bfloat162 ll; ll.x = l0; ll.y = l1;
    whi = *reinterpret_cast<uint32_t*>(&hh);
    wlo = *reinterpret_cast<uint32_t*>(&ll);
}
__device__ __forceinline__ void mma16(float* d_, const uint32_t* a, const uint32_t* b) {
    asm volatile(
        "mma.sync.aligned.m16n8k16.row.col.f32.bf16.bf16.f32 "
        "{%0,%1,%2,%3}, {%4,%5,%6,%7}, {%8,%9}, {%0,%1,%2,%3};"
        : "+f"(d_[0]), "+f"(d_[1]), "+f"(d_[2]), "+f"(d_[3])
        : "r"(a[0]), "r"(a[1]), "r"(a[2]), "r"(a[3]), "r"(b[0]), "r"(b[1]));
}

// ============================================================
// Kernel 0a: compaction of valid k columns per b.
// ============================================================
__global__ void compact_kernel(const int* __restrict__ pm) {
    int b = blockIdx.x;
    int t = threadIdx.x;
    __shared__ int wcnt[10], woff[10];
    int valid = (pm[(size_t)t * NSEQ + b] > 0) ? 1 : 0;
    unsigned ball = __ballot_sync(0xffffffffu, valid);
    int warp = t >> 5, lane = t & 31;
    if (lane == 0) wcnt[warp] = __popc(ball);
    __syncthreads();
    if (t == 0) {
        int s = 0;
        #pragma unroll
        for (int w = 0; w < 10; w++) { woff[w] = s; s += wcnt[w]; }
        g_cnt[b] = s;
    }
    __syncthreads();
    if (valid) {
        int pos = woff[warp] + __popc(ball & ((1u << lane) - 1u));
        g_idx[b * NSEQ + pos] = t;
    }
}

// ============================================================
// Kernel 0b: bf16 weights — proj + wout, both transposed [n][kw].
// ============================================================
__global__ void wsplit(const float* __restrict__ wq, const float* __restrict__ wk,
                       const float* __restrict__ wv, const float* __restrict__ wg,
                       const float* __restrict__ wout) {
    int i = blockIdx.x * 256 + threadIdx.x;   // 0..40959
    if (i < 4 * C * CW) {
        int op = i >> 13, rem = i & 8191;
        int n = rem >> 6, kw = rem & 63;
        const float* W = (op == 0) ? wq : (op == 1) ? wk : (op == 2) ? wv : wg;
        float v0 = W[(size_t)(2*kw) * C + n];
        float v1 = W[(size_t)(2*kw+1) * C + n];
        uint32_t wh, wl; split2(v0, v1, wh, wl);
        g_wth[i] = wh; g_wtl[i] = wl;
    } else if (i < 4 * C * CW + C * CW) {
        int j = i - 4 * C * CW;
        int n = j >> 6, kw = j & 63;
        float v0 = wout[(size_t)n * C + 2*kw];
        float v1 = wout[(size_t)n * C + 2*kw + 1];
        uint32_t wh, wl; split2(v0, v1, wh, wl);
        g_woth[j] = wh; g_wotl[j] = wl;
    }
}

// ============================================================
// Kernel 1: LayerNorm (bf16 packed planes) + pair-bias.
// ============================================================
__global__ void ln_bias_kernel(const float* __restrict__ act,
                               const float* __restrict__ gamma,
                               const float* __restrict__ beta,
                               const float* __restrict__ wpb) {
    int warp = (blockIdx.x * blockDim.x + threadIdx.x) >> 5;
    int lane = threadIdx.x & 31;
    if (warp >= NN) return;
    const float4* a = (const float4*)(act + (size_t)warp * C);
    float4 v = a[lane];
    float s  = v.x + v.y + v.z + v.w;
    float s2 = v.x*v.x + v.y*v.y + v.z*v.z + v.w*v.w;
    #pragma unroll
    for (int o = 16; o > 0; o >>= 1) {
        s  += __shfl_xor_sync(0xffffffffu, s,  o);
        s2 += __shfl_xor_sync(0xffffffffu, s2, o);
    }
    float mu  = s * (1.0f / C);
    float var = s2 * (1.0f / C) - mu * mu;
    float r = rsqrtf(var + LN_EPS);
    float4 g = ((const float4*)gamma)[lane];
    float4 b = ((const float4*)beta)[lane];
    float4 o;
    o.x = (v.x - mu) * r * g.x + b.x;
    o.y = (v.y - mu) * r * g.y + b.y;
    o.z = (v.z - mu) * r * g.z + b.z;
    o.w = (v.w - mu) * r * g.w + b.w;
    uint32_t w0h, w0l, w1h, w1l;
    split2(o.x, o.y, w0h, w0l);
    split2(o.z, o.w, w1h, w1l);
    *(uint2*)(g_xh + (size_t)warp * CW + 2*lane) = make_uint2(w0h, w1h);
    *(uint2*)(g_xl + (size_t)warp * CW + 2*lane) = make_uint2(w0l, w1l);

    const float4* wb = (const float4*)(wpb + lane * 16);
    float4 w0 = wb[0], w1 = wb[1], w2 = wb[2], w3 = wb[3];
    float bh[4];
    bh[0] = o.x*w0.x + o.y*w1.x + o.z*w2.x + o.w*w3.x;
    bh[1] = o.x*w0.y + o.y*w1.y + o.z*w2.y + o.w*w3.y;
    bh[2] = o.x*w0.z + o.y*w1.z + o.z*w2.z + o.w*w3.z;
    bh[3] = o.x*w0.w + o.y*w1.w + o.z*w2.w + o.w*w3.w;
    #pragma unroll
    for (int h = 0; h < 4; h++) {
        #pragma unroll
        for (int off = 16; off > 0; off >>= 1)
            bh[h] += __shfl_xor_sync(0xffffffffu, bh[h], off);
    }
    if (lane == 0) {
        int qi = warp / NSEQ;
        int kj = warp - qi * NSEQ;
        #pragma unroll
        for (int h = 0; h < 4; h++)
            g_bias[h*NN + kj*NSEQ + qi] = bh[h];
    }
}

// ============================================================
// Kernel 2: projection GEMMs, bf16 3-term m16n8k16 (R15 verbatim).
// ============================================================
#define SA 20

__global__ void __launch_bounds__(256, 2)
proj_mma() {
    __shared__ __align__(16) uint32_t Ah[128*SA], Al[128*SA];
    __shared__ __align__(16) uint32_t Bh[128*SA], Bl[128*SA];
    int op = blockIdx.x;
    const uint32_t* Wth = g_wth + op * C * CW;
    const uint32_t* Wtl = g_wtl + op * C * CW;
    int bm = blockIdx.y * 128;
    int tid = threadIdx.x;
    int wid = tid >> 5, lane = tid & 31;
    int wm = (wid >> 2) * 64, wn = (wid & 3) * 32;
    int lr = lane >> 2, lc = lane & 3;

    float acc[4][4][4];
    #pragma unroll
    for (int mi = 0; mi < 4; mi++)
        #pragma unroll
        for (int ni = 0; ni < 4; ni++)
            #pragma unroll
            for (int e = 0; e < 4; e++) acc[mi][ni][e] = 0.0f;

    for (int k0w = 0; k0w < CW; k0w += 16) {
        #pragma unroll
        for (int i = 0; i < 2; i++) {
            int e = i * 256 + tid;
            int r = e >> 2, q4 = (e & 3) * 4;
            *(uint4*)&Ah[r*SA + q4] = *(const uint4*)(g_xh + (size_t)(bm + r) * CW + k0w + q4);
            *(uint4*)&Al[r*SA + q4] = *(const uint4*)(g_xl + (size_t)(bm + r) * CW + k0w + q4);
            *(uint4*)&Bh[r*SA + q4] = *(const uint4*)(Wth + (size_t)r * CW + k0w + q4);
            *(uint4*)&Bl[r*SA + q4] = *(const uint4*)(Wtl + (size_t)r * CW + k0w + q4);
        }
        __syncthreads();
        #pragma unroll
        for (int kc = 0; kc < 2; kc++) {
            int wb = kc * 8;
            uint32_t ah[4][4], al[4][4];
            #pragma unroll
            for (int mi = 0; mi < 4; mi++) {
                int r0 = wm + mi * 16 + lr;
                ah[mi][0] = Ah[r0*SA + wb + lc];
                ah[mi][1] = Ah[(r0+8)*SA + wb + lc];
                ah[mi][2] = Ah[r0*SA + wb + lc + 4];
                ah[mi][3] = Ah[(r0+8)*SA + wb + lc + 4];
                al[mi][0] = Al[r0*SA + wb + lc];
                al[mi][1] = Al[(r0+8)*SA + wb + lc];
                al[mi][2] = Al[r0*SA + wb + lc + 4];
                al[mi][3] = Al[(r0+8)*SA + wb + lc + 4];
            }
            uint32_t bh2[4][2], bl2[4][2];
            #pragma unroll
            for (int ni = 0; ni < 4; ni++) {
                int n0 = wn + ni * 8 + lr;
                bh2[ni][0] = Bh[n0*SA + wb + lc];
                bh2[ni][1] = Bh[n0*SA + wb + lc + 4];
                bl2[ni][0] = Bl[n0*SA + wb + lc];
                bl2[ni][1] = Bl[n0*SA + wb + lc + 4];
            }
            #pragma unroll
            for (int mi = 0; mi < 4; mi++)
                #pragma unroll
                for (int ni = 0; ni < 4; ni++) {
                    mma16(acc[mi][ni], ah[mi], bh2[ni]);
                    mma16(acc[mi][ni], ah[mi], bl2[ni]);
                    mma16(acc[mi][ni], al[mi], bh2[ni]);
                }
        }
        __syncthreads();
    }

    const float qscale = 0.17677669529663687f;
    #pragma unroll
    for (int mi = 0; mi < 4; mi++) {
        #pragma unroll
        for (int ni = 0; ni < 4; ni++) {
            int row = bm + wm + mi * 16 + lr;
            int col = wn + ni * 8 + 2 * lc;
            float v0 = acc[mi][ni][0], v1 = acc[mi][ni][1];
            float v2 = acc[mi][ni][2], v3 = acc[mi][ni][3];
            size_t o0 = (size_t)row * C + col;
            size_t o1 = (size_t)(row + 8) * C + col;
            if (op == 0) {
                *(float2*)(g_q + o0) = make_float2(v0*qscale, v1*qscale);
                *(float2*)(g_q + o1) = make_float2(v2*qscale, v3*qscale);
            } else if (op == 3) {
                *(float2*)(g_gate + o0) = make_float2(1.0f/(1.0f+__expf(-v0)),
                                                      1.0f/(1.0f+__expf(-v1)));
                *(float2*)(g_gate + o1) = make_float2(1.0f/(1.0f+__expf(-v2)),
                                                      1.0f/(1.0f+__expf(-v3)));
            } else {
                float* dhi = (op == 1) ? g_khi : g_vhi;
                float* dlo = (op == 1) ? g_klo : g_vlo;
                uint32_t h0,l0,h1,l1,h2,l2,h3,l3;
                split_tf32(v0,h0,l0); split_tf32(v1,h1,l1);
                split_tf32(v2,h2,l2); split_tf32(v3,h3,l3);
                *(float2*)(dhi + o0) = make_float2(__uint_as_float(h0), __uint_as_float(h1));
                *(float2*)(dlo + o0) = make_float2(__uint_as_float(l0), __uint_as_float(l1));
                *(float2*)(dhi + o1) = make_float2(__uint_as_float(h2), __uint_as_float(h3));
                *(float2*)(dlo + o1) = make_float2(__uint_as_float(l2), __uint_as_float(l3));
            }
        }
    }
}

// ============================================================
// Kernel 3: tensor attention — R15 numerics VERBATIM (tf32 S with
// bias preloaded, tf32 PV), ONLY the K/V/idx staging is pipelined
// through registers (prefetch next chunk during current compute).
// ============================================================
#define KC 16
#define VS 20
#define PS 20

__global__ void __launch_bounds__(320, 1)
attn_mma() {
    __shared__ __align__(16) float Khi[KC*36], Klo[KC*36];
    __shared__ __align__(16) float Vthi[D*VS], Vtlo[D*VS];
    __shared__ float Ps[10][32*PS];
    __shared__ int idxs[KC];

    int b = blockIdx.x, h = blockIdx.y;
    int tid = threadIdx.x, wid = tid >> 5, lane = tid & 31;
    int lr = lane >> 2, lc = lane & 3;
    int cnt = g_cnt[b];
    const int* idxp = g_idx + b * NSEQ;
    const float* bhp = g_bias + (size_t)h * NN;
    int qbl = wid * 32;

    uint32_t qhi[2][4][4], qlo[2][4][4];
    {
        const float* qp = g_q + (size_t)(b * NSEQ) * C + h * D;
        #pragma unroll
        for (int mi = 0; mi < 2; mi++) {
            int r0 = qbl + mi * 16 + lr;
            #pragma unroll
            for (int kcc = 0; kcc < 4; kcc++) {
                int c0 = kcc * 8 + lc;
                split_tf32(qp[(size_t)r0 * C + c0],         qhi[mi][kcc][0], qlo[mi][kcc][0]);
                split_tf32(qp[(size_t)(r0 + 8) * C + c0],   qhi[mi][kcc][1], qlo[mi][kcc][1]);
                split_tf32(qp[(size_t)r0 * C + c0 + 4],     qhi[mi][kcc][2], qlo[mi][kcc][2]);
                split_tf32(qp[(size_t)(r0 + 8) * C + c0+4], qhi[mi][kcc][3], qlo[mi][kcc][3]);
            }
        }
    }

    float acc[2][4][4];
    #pragma unroll
    for (int mi = 0; mi < 2; mi++)
        #pragma unroll
        for (int ni = 0; ni < 4; ni++)
            #pragma unroll
            for (int e = 0; e < 4; e++) acc[mi][ni][e] = 0.0f;
    float lsum[2][2] = {{0.0f, 0.0f}, {0.0f, 0.0f}};

    int nch = (cnt + KC - 1) >> 4;
    int skey = tid >> 3, sg = tid & 7;   // staging role for tid < 128

    // ---- prefetch chunk 0 into registers ----
    float4 pkh = make_float4(0,0,0,0), pkl = make_float4(0,0,0,0);
    float4 pvh = make_float4(0,0,0,0), pvl = make_float4(0,0,0,0);
    int pidx = 0;
    if (tid < 128) {
        int kg = (skey < cnt) ? idxp[skey] : idxp[0];
        size_t base = ((size_t)(b * NSEQ) + kg) * C + h * D + sg * 4;
        pkh = *(const float4*)(g_khi + base);
        pkl = *(const float4*)(g_klo + base);
        pvh = *(const float4*)(g_vhi + base);
        pvl = *(const float4*)(g_vlo + base);
    }
    if (tid < KC) pidx = (tid < cnt) ? idxp[tid] : idxp[0];

    for (int ch = 0; ch < nch; ch++) {
        int jc = ch << 4;
        __syncthreads();
        if (tid < 128) {
            int dd = sg * 4;
            *(float4*)&Khi[skey*36 + dd] = pkh;
            *(float4*)&Klo[skey*36 + dd] = pkl;
            Vthi[(dd+0)*VS + skey] = pvh.x; Vtlo[(dd+0)*VS + skey] = pvl.x;
            Vthi[(dd+1)*VS + skey] = pvh.y; Vtlo[(dd+1)*VS + skey] = pvl.y;
            Vthi[(dd+2)*VS + skey] = pvh.z; Vtlo[(dd+2)*VS + skey] = pvl.z;
            Vthi[(dd+3)*VS + skey] = pvh.w; Vtlo[(dd+3)*VS + skey] = pvl.w;
        }
        if (tid < KC) idxs[tid] = pidx;
        // prefetch next chunk (overlaps this chunk's compute)
        if (ch + 1 < nch) {
            if (tid < 128) {
                int j = jc + KC + skey;
                int kg = (j < cnt) ? idxp[j] : idxp[0];
                size_t base = ((size_t)(b * NSEQ) + kg) * C + h * D + sg * 4;
                pkh = *(const float4*)(g_khi + base);
                pkl = *(const float4*)(g_klo + base);
                pvh = *(const float4*)(g_vhi + base);
                pvl = *(const float4*)(g_vlo + base);
            }
            if (tid < KC) {
                int j = jc + KC + tid;
                pidx = (j < cnt) ? idxp[j] : idxp[0];
            }
        }
        __syncthreads();

        float sc[2][2][4];
        #pragma unroll
        for (int ni = 0; ni < 2; ni++) {
            int kl_ = ni * 8 + 2 * lc;
            bool ok0 = (jc + kl_ < cnt), ok1 = (jc + kl_ + 1 < cnt);
            int kg0 = idxs[kl_], kg1 = idxs[kl_ + 1];
            #pragma unroll
            for (int mi = 0; mi < 2; mi++) {
                int q0 = qbl + mi * 16 + lr;
                sc[mi][ni][0] = ok0 ? bhp[(size_t)kg0 * NSEQ + q0]     : -1e4f;
                sc[mi][ni][1] = ok1 ? bhp[(size_t)kg1 * NSEQ + q0]     : -1e4f;
                sc[mi][ni][2] = ok0 ? bhp[(size_t)kg0 * NSEQ + q0 + 8] : -1e4f;
                sc[mi][ni][3] = ok1 ? bhp[(size_t)kg1 * NSEQ + q0 + 8] : -1e4f;
            }
        }
        #pragma unroll
        for (int kcc = 0; kcc < 4; kcc++) {
            int kb = kcc * 8 + lc;
            uint32_t bh2[2][2], bl2[2][2];
            #pragma unroll
            for (int ni = 0; ni < 2; ni++) {
                int n0 = ni * 8 + lr;
                bh2[ni][0] = __float_as_uint(Khi[n0*36 + kb]);
                bh2[ni][1] = __float_as_uint(Khi[n0*36 + kb + 4]);
                bl2[ni][0] = __float_as_uint(Klo[n0*36 + kb]);
                bl2[ni][1] = __float_as_uint(Klo[n0*36 + kb + 4]);
            }
            #pragma unroll
            for (int mi = 0; mi < 2; mi++)
                #pragma unroll
                for (int ni = 0; ni < 2; ni++) {
                    mma8(sc[mi][ni], qhi[mi][kcc], bh2[ni]);
                    mma8(sc[mi][ni], qhi[mi][kcc], bl2[ni]);
                    mma8(sc[mi][ni], qlo[mi][kcc], bh2[ni]);
                }
        }
        #pragma unroll
        for (int mi = 0; mi < 2; mi++)
            #pragma unroll
            for (int ni = 0; ni < 2; ni++) {
                float p0 = __expf(sc[mi][ni][0]);
                float p1 = __expf(sc[mi][ni][1]);
                float p2 = __expf(sc[mi][ni][2]);
                float p3 = __expf(sc[mi][ni][3]);
                lsum[mi][0] += p0 + p1;
                lsum[mi][1] += p2 + p3;
                int r0 = mi * 16 + lr, cc = ni * 8 + 2 * lc;
                Ps[wid][r0*PS + cc] = p0;       Ps[wid][r0*PS + cc + 1] = p1;
                Ps[wid][(r0+8)*PS + cc] = p2;   Ps[wid][(r0+8)*PS + cc + 1] = p3;
            }
        __syncwarp();
        #pragma unroll
        for (int kcc = 0; kcc < 2; kcc++) {
            int kb = kcc * 8 + lc;
            uint32_t phi[2][4], plo[2][4];
            #pragma unroll
            for (int mi = 0; mi < 2; mi++) {
                int r0 = mi * 16 + lr;
                split_tf32(Ps[wid][r0*PS + kb],         phi[mi][0], plo[mi][0]);
                split_tf32(Ps[wid][(r0+8)*PS + kb],     phi[mi][1], plo[mi][1]);
                split_tf32(Ps[wid][r0*PS + kb + 4],     phi[mi][2], plo[mi][2]);
                split_tf32(Ps[wid][(r0+8)*PS + kb + 4], phi[mi][3], plo[mi][3]);
            }
            #pragma unroll
            for (int ni = 0; ni < 4; ni++) {
                int n0 = ni * 8 + lr;
                uint32_t vh2[2] = { __float_as_uint(Vthi[n0*VS + kb]),
                                    __float_as_uint(Vthi[n0*VS + kb + 4]) };
                uint32_t vl2[2] = { __float_as_uint(Vtlo[n0*VS + kb]),
                                    __float_as_uint(Vtlo[n0*VS + kb + 4]) };
                #pragma unroll
                for (int mi = 0; mi < 2; mi++) {
                    mma8(acc[mi][ni], phi[mi], vh2);
                    mma8(acc[mi][ni], phi[mi], vl2);
                    mma8(acc[mi][ni], plo[mi], vh2);
                }
            }
        }
        __syncwarp();
    }

    float inv[2][2];
    #pragma unroll
    for (int mi = 0; mi < 2; mi++)
        #pragma unroll
        for (int e = 0; e < 2; e++) {
            float lf = lsum[mi][e];
            lf += __shfl_xor_sync(0xffffffffu, lf, 1);
            lf += __shfl_xor_sync(0xffffffffu, lf, 2);
            inv[mi][e] = (lf > 0.0f) ? 1.0f / lf : 0.0f;
        }
    #pragma unroll
    for (int mi = 0; mi < 2; mi++) {
        int qg = b * NSEQ + qbl + mi * 16 + lr;
        #pragma unroll
        for (int ni = 0; ni < 4; ni++) {
            int dcol = h * D + ni * 8 + 2 * lc;
            size_t o0 = (size_t)qg * C + dcol;
            size_t o1 = o0 + (size_t)8 * C;
            float2 gt0 = *(const float2*)(g_gate + o0);
            float2 gt1 = *(const float2*)(g_gate + o1);
            float v0 = acc[mi][ni][0] * inv[mi][0] * gt0.x;
            float v1 = acc[mi][ni][1] * inv[mi][0] * gt0.y;
            float v2 = acc[mi][ni][2] * inv[mi][1] * gt1.x;
            float v3 = acc[mi][ni][3] * inv[mi][1] * gt1.y;
            int wc = dcol >> 1;
            uint32_t wh, wl;
            split2(v0, v1, wh, wl);
            g_wah[(size_t)qg * CW + wc] = wh;
            g_wal[(size_t)qg * CW + wc] = wl;
            split2(v2, v3, wh, wl);
            g_wah[(size_t)(qg + 8) * CW + wc] = wh;
            g_wal[(size_t)(qg + 8) * CW + wc] = wl;
        }
    }
}

// ============================================================
// Kernel 4: output GEMM, bf16 3-term (R15 verbatim).
// ============================================================
__global__ void __launch_bounds__(256, 2)
out_mma(float* __restrict__ out) {
    __shared__ __align__(16) uint32_t Ah[128*SA], Al[128*SA];
    __shared__ __align__(16) uint32_t Bh[128*SA], Bl[128*SA];
    int bm = blockIdx.x * 128;
    int tid = threadIdx.x;
    int wid = tid >> 5, lane = tid & 31;
    int wm = (wid >> 2) * 64, wn = (wid & 3) * 32;
    int lr = lane >> 2, lc = lane & 3;

    float acc[4][4][4];
    #pragma unroll
    for (int mi = 0; mi < 4; mi++)
        #pragma unroll
        for (int ni = 0; ni < 4; ni++)
            #pragma unroll
            for (int e = 0; e < 4; e++) acc[mi][ni][e] = 0.0f;

    for (int k0w = 0; k0w < CW; k0w += 16) {
        #pragma unroll
        for (int i = 0; i < 2; i++) {
            int e = i * 256 + tid;
            int r = e >> 2, q4 = (e & 3) * 4;
            *(uint4*)&Ah[r*SA + q4] = *(const uint4*)(g_wah + (size_t)(bm + r) * CW + k0w + q4);
            *(uint4*)&Al[r*SA + q4] = *(const uint4*)(g_wal + (size_t)(bm + r) * CW + k0w + q4);
            *(uint4*)&Bh[r*SA + q4] = *(const uint4*)(g_woth + (size_t)r * CW + k0w + q4);
            *(uint4*)&Bl[r*SA + q4] = *(const uint4*)(g_wotl + (size_t)r * CW + k0w + q4);
        }
        __syncthreads();
        #pragma unroll
        for (int kc = 0; kc < 2; kc++) {
            int wb = kc * 8;
            uint32_t ah[4][4], al[4][4];
            #pragma unroll
            for (int mi = 0; mi < 4; mi++) {
                int r0 = wm + mi * 16 + lr;
                ah[mi][0] = Ah[r0*SA + wb + lc];
                ah[mi][1] = Ah[(r0+8)*SA + wb + lc];
                ah[mi][2] = Ah[r0*SA + wb + lc + 4];
                ah[mi][3] = Ah[(r0+8)*SA + wb + lc + 4];
                al[mi][0] = Al[r0*SA + wb + lc];
                al[mi][1] = Al[(r0+8)*SA + wb + lc];
                al[mi][2] = Al[r0*SA + wb + lc + 4];
                al[mi][3] = Al[(r0+8)*SA + wb + lc + 4];
            }
            uint32_t bh2[4][2], bl2[4][2];
            #pragma unroll
            for (int ni = 0; ni < 4; ni++) {
                int n0 = wn + ni * 8 + lr;
                bh2[ni][0] = Bh[n0*SA + wb + lc];
                bh2[ni][1] = Bh[n0*SA + wb + lc + 4];
                bl2[ni][0] = Bl[n0*SA + wb + lc];
                bl2[ni][1] = Bl[n0*SA + wb + lc + 4];
            }
            #pragma unroll
            for (int mi = 0; mi < 4; mi++)
                #pragma unroll
                for (int ni = 0; ni < 4; ni++) {
                    mma16(acc[mi][ni], ah[mi], bh2[ni]);
                    mma16(acc[mi][ni], ah[mi], bl2[ni]);
                    mma16(acc[mi][ni], al[mi], bh2[ni]);
                }
        }
        __syncthreads();
    }

    #pragma unroll
    for (int mi = 0; mi < 4; mi++) {
        #pragma unroll
        for (int ni = 0; ni < 4; ni++) {
            int row = bm + wm + mi * 16 + lr;
            int col = wn + ni * 8 + 2 * lc;
            *(float2*)(out + (size_t)row * C + col)
                = make_float2(acc[mi][ni][0], acc[mi][ni][1]);
            *(float2*)(out + (size_t)(row+8) * C + col)
                = make_float2(acc[mi][ni][2], acc[mi][ni][3]);
        }
    }
}

// ============================================================
extern "C" void kernel_launch(void* const* d_in, const int* in_sizes, int n_in,
                              void* d_out, int out_size) {
    const float* act   = (const float*)d_in[0];
    const int*   pmask = (const int*)  d_in[1];
    const float* gamma = (const float*)d_in[2];
    const float* beta  = (const float*)d_in[3];
    const float* wpb   = (const float*)d_in[4];
    const float* wq    = (const float*)d_in[5];
    const float* wk    = (const float*)d_in[6];
    const float* wv    = (const float*)d_in[7];
    const float* wg    = (const float*)d_in[8];
    const float* wout  = (const float*)d_in[9];
    float* out = (float*)d_out;

    compact_kernel<<<NSEQ, NSEQ>>>(pmask);
    wsplit<<<160, 256>>>(wq, wk, wv, wg, wout);
    ln_bias_kernel<<<NN/8, 256>>>(act, gamma, beta, wpb);
    proj_mma<<<dim3(4, NN/128), 256>>>();
    attn_mma<<<dim3(NSEQ, H), 320>>>();
    out_mma<<<NN/128, 256>>>(out);
}